// round 1
// baseline (speedup 1.0000x reference)
#include <cuda_runtime.h>

// Problem constants (fixed by reference: B=4, S=2048, D=1024, H=16)
#define DD     1024
#define NH     16
#define HD     64
#define BATCH  4
#define SEQ    2048
#define MTOT   (BATCH * SEQ)      // 8192
#define CHUNK  64
#define NCHUNK (SEQ / CHUNK)      // 32
#define NBH    (BATCH * NH)       // 64

// Scratch (allocation-free rule: __device__ globals)
__device__ float g_Q  [MTOT * DD];
__device__ float g_Kb [MTOT * DD];
__device__ float g_Vb [MTOT * DD];
__device__ float g_VAL[MTOT * DD];
__device__ float g_KV [NBH * NCHUNK * HD * HD];
__device__ float g_KS [NBH * NCHUNK * HD];

// ---------------------------------------------------------------------------
// GEMM: C = act(A[M,K] @ W[K,N] + bias[N]);  ACT=1 applies phi(x)=elu(x)+1
// 128x128 tile, BK=16, 256 threads, 8x8 micro-tile, register-staged prefetch.
// ---------------------------------------------------------------------------
template<int ACT>
__global__ __launch_bounds__(256, 2)
void gemm_k(const float* __restrict__ Ag, const float* __restrict__ Wg,
            const float* __restrict__ bias, float* __restrict__ Cg,
            int M, int N, int K)
{
    constexpr int TM = 128, TN = 128, BK = 16;
    __shared__ __align__(16) float As[BK][TM + 4];   // transposed A tile
    __shared__ __align__(16) float Bs[BK][TN];

    const int tid = threadIdx.x;
    const int m0 = blockIdx.y * TM;
    const int n0 = blockIdx.x * TN;
    const int ty = tid >> 4;           // 0..15 -> rows ty*8..
    const int tx = tid & 15;           // 0..15 -> cols tx*8..

    const int ar = tid >> 2;           // 0..63 : A row (two rows: ar, ar+64)
    const int ac = (tid & 3) * 4;      // 0,4,8,12 : A k-subcol
    const int br = tid >> 5;           // 0..7  : B k-row (two: br, br+8)
    const int bc = (tid & 31) * 4;     // 0..124 : B n-subcol

    const float* Abase = Ag + (size_t)m0 * K;

    float4 pa0 = *(const float4*)(Abase + (size_t)ar * K + ac);
    float4 pa1 = *(const float4*)(Abase + (size_t)(ar + 64) * K + ac);
    float4 pb0 = *(const float4*)(Wg + (size_t)br * N + n0 + bc);
    float4 pb1 = *(const float4*)(Wg + (size_t)(br + 8) * N + n0 + bc);

    float acc[8][8];
    #pragma unroll
    for (int i = 0; i < 8; i++)
        #pragma unroll
        for (int j = 0; j < 8; j++) acc[i][j] = 0.f;

    for (int kt = 0; kt < K; kt += BK) {
        // commit staged tile to smem
        As[ac + 0][ar] = pa0.x; As[ac + 1][ar] = pa0.y;
        As[ac + 2][ar] = pa0.z; As[ac + 3][ar] = pa0.w;
        As[ac + 0][ar + 64] = pa1.x; As[ac + 1][ar + 64] = pa1.y;
        As[ac + 2][ar + 64] = pa1.z; As[ac + 3][ar + 64] = pa1.w;
        *(float4*)&Bs[br][bc]     = pb0;
        *(float4*)&Bs[br + 8][bc] = pb1;
        __syncthreads();

        const int kn = kt + BK;
        if (kn < K) {  // prefetch next tile while computing current
            pa0 = *(const float4*)(Abase + (size_t)ar * K + kn + ac);
            pa1 = *(const float4*)(Abase + (size_t)(ar + 64) * K + kn + ac);
            pb0 = *(const float4*)(Wg + (size_t)(kn + br) * N + n0 + bc);
            pb1 = *(const float4*)(Wg + (size_t)(kn + br + 8) * N + n0 + bc);
        }

        #pragma unroll
        for (int kk = 0; kk < BK; kk++) {
            float a[8], b[8];
            *(float4*)&a[0] = *(const float4*)&As[kk][ty * 8];
            *(float4*)&a[4] = *(const float4*)&As[kk][ty * 8 + 4];
            *(float4*)&b[0] = *(const float4*)&Bs[kk][tx * 8];
            *(float4*)&b[4] = *(const float4*)&Bs[kk][tx * 8 + 4];
            #pragma unroll
            for (int i = 0; i < 8; i++)
                #pragma unroll
                for (int j = 0; j < 8; j++)
                    acc[i][j] = fmaf(a[i], b[j], acc[i][j]);
        }
        __syncthreads();
    }

    float bvv[8];
    #pragma unroll
    for (int j = 0; j < 8; j++) bvv[j] = bias[n0 + tx * 8 + j];

    #pragma unroll
    for (int i = 0; i < 8; i++) {
        float outv[8];
        #pragma unroll
        for (int j = 0; j < 8; j++) {
            float v = acc[i][j] + bvv[j];
            if (ACT) v = (v > 0.f) ? (v + 1.f) : __expf(v);  // elu(x)+1
            outv[j] = v;
        }
        float* cp = Cg + (size_t)(m0 + ty * 8 + i) * N + n0 + tx * 8;
        *(float4*)cp       = *(float4*)&outv[0];
        *(float4*)(cp + 4) = *(float4*)&outv[4];
    }
}

// ---------------------------------------------------------------------------
// Pass A: per (bh, chunk): KV_c[d][m] = sum_t K[t][d]*V[t][m];  ks_c[d]=sum_t K[t][d]
// ---------------------------------------------------------------------------
__global__ __launch_bounds__(256)
void kv_chunk_k()
{
    const int c = blockIdx.x, bh = blockIdx.y;
    const int b = bh >> 4, h = bh & 15;
    __shared__ float Ks[CHUNK][HD + 1];
    __shared__ float Vs[CHUNK][HD + 1];
    const int tid = threadIdx.x;
    const size_t rowbase = (size_t)(b * SEQ + c * CHUNK) * DD + h * HD;

    for (int i = tid; i < CHUNK * (HD / 4); i += 256) {
        const int t = i >> 4;
        const int d4 = (i & 15) * 4;
        float4 kq = *(const float4*)(g_Kb + rowbase + (size_t)t * DD + d4);
        Ks[t][d4] = kq.x; Ks[t][d4+1] = kq.y; Ks[t][d4+2] = kq.z; Ks[t][d4+3] = kq.w;
        float4 vq = *(const float4*)(g_Vb + rowbase + (size_t)t * DD + d4);
        Vs[t][d4] = vq.x; Vs[t][d4+1] = vq.y; Vs[t][d4+2] = vq.z; Vs[t][d4+3] = vq.w;
    }
    __syncthreads();

    const int ty = tid >> 4, tx = tid & 15;   // d-block ty*4, m-block tx*4
    float acc[4][4];
    #pragma unroll
    for (int i = 0; i < 4; i++)
        #pragma unroll
        for (int j = 0; j < 4; j++) acc[i][j] = 0.f;

    for (int t = 0; t < CHUNK; t++) {
        float kr[4], vr[4];
        #pragma unroll
        for (int i = 0; i < 4; i++) { kr[i] = Ks[t][ty * 4 + i]; vr[i] = Vs[t][tx * 4 + i]; }
        #pragma unroll
        for (int i = 0; i < 4; i++)
            #pragma unroll
            for (int j = 0; j < 4; j++)
                acc[i][j] = fmaf(kr[i], vr[j], acc[i][j]);
    }

    float* outp = g_KV + (size_t)(bh * NCHUNK + c) * HD * HD;
    #pragma unroll
    for (int i = 0; i < 4; i++)
        #pragma unroll
        for (int j = 0; j < 4; j++)
            outp[(ty * 4 + i) * HD + tx * 4 + j] = acc[i][j];

    if (tid < HD) {
        float s = 0.f;
        for (int t = 0; t < CHUNK; t++) s += Ks[t][tid];
        g_KS[(bh * NCHUNK + c) * HD + tid] = s;
    }
}

// ---------------------------------------------------------------------------
// Pass B: in-place EXCLUSIVE prefix over chunks (per bh): state and z
// ---------------------------------------------------------------------------
__global__ __launch_bounds__(1024)
void prefix_k()
{
    const int bh = blockIdx.x;
    const int tid = threadIdx.x;
    float4 run = make_float4(0.f, 0.f, 0.f, 0.f);
    float* base = g_KV + (size_t)bh * NCHUNK * HD * HD;
    for (int c = 0; c < NCHUNK; c++) {
        float4* p = (float4*)(base + (size_t)c * HD * HD) + tid;
        float4 v = *p;
        *p = run;
        run.x += v.x; run.y += v.y; run.z += v.z; run.w += v.w;
    }
    if (tid < HD) {
        float r = 0.f;
        float* zb = g_KS + (size_t)bh * NCHUNK * HD + tid;
        for (int c = 0; c < NCHUNK; c++) { float v = zb[(size_t)c * HD]; zb[(size_t)c * HD] = r; r += v; }
    }
}

// ---------------------------------------------------------------------------
// Pass C: per (bh, chunk): out = (tril(QK^T) V + Q S_prev) / (rowsum + Q.z_prev + eps)
// ---------------------------------------------------------------------------
__global__ __launch_bounds__(256)
void attn_out_k()
{
    extern __shared__ float sm[];
    float (*Qs) [HD + 1]    = (float(*)[HD + 1])sm;
    float (*KVs)[HD + 1]    = (float(*)[HD + 1])(sm + CHUNK * (HD + 1));       // K, then reused for V
    float (*Ss) [HD + 1]    = (float(*)[HD + 1])(sm + 2 * CHUNK * (HD + 1));   // S_prev[d][m]
    float (*Asc)[CHUNK + 1] = (float(*)[CHUNK + 1])(sm + 3 * CHUNK * (HD + 1));
    float* den = sm + 3 * CHUNK * (HD + 1) + CHUNK * (CHUNK + 1);
    float* zp  = den + CHUNK;

    const int c = blockIdx.x, bh = blockIdx.y;
    const int b = bh >> 4, h = bh & 15;
    const int tid = threadIdx.x;
    const size_t rowbase = (size_t)(b * SEQ + c * CHUNK) * DD + h * HD;
    const float* Sp = g_KV + (size_t)(bh * NCHUNK + c) * HD * HD;

    for (int i = tid; i < CHUNK * (HD / 4); i += 256) {
        const int t = i >> 4;
        const int d4 = (i & 15) * 4;
        float4 q = *(const float4*)(g_Q  + rowbase + (size_t)t * DD + d4);
        Qs[t][d4] = q.x; Qs[t][d4+1] = q.y; Qs[t][d4+2] = q.z; Qs[t][d4+3] = q.w;
        float4 k = *(const float4*)(g_Kb + rowbase + (size_t)t * DD + d4);
        KVs[t][d4] = k.x; KVs[t][d4+1] = k.y; KVs[t][d4+2] = k.z; KVs[t][d4+3] = k.w;
        float4 s = *(const float4*)(Sp + (size_t)t * HD + d4);   // CHUNK==HD rows
        Ss[t][d4] = s.x; Ss[t][d4+1] = s.y; Ss[t][d4+2] = s.z; Ss[t][d4+3] = s.w;
    }
    if (tid < HD) zp[tid] = g_KS[(bh * NCHUNK + c) * HD + tid];
    __syncthreads();

    const int ty = tid >> 4, tx = tid & 15;

    // Phase 1: masked scores A[t][u] = (u<=t) ? q_t . k_u : 0
    {
        float acc[4][4];
        #pragma unroll
        for (int i = 0; i < 4; i++)
            #pragma unroll
            for (int j = 0; j < 4; j++) acc[i][j] = 0.f;
        for (int d = 0; d < HD; d++) {
            float q[4], k[4];
            #pragma unroll
            for (int i = 0; i < 4; i++) { q[i] = Qs[ty * 4 + i][d]; k[i] = KVs[tx * 4 + i][d]; }
            #pragma unroll
            for (int i = 0; i < 4; i++)
                #pragma unroll
                for (int j = 0; j < 4; j++)
                    acc[i][j] = fmaf(q[i], k[j], acc[i][j]);
        }
        #pragma unroll
        for (int i = 0; i < 4; i++)
            #pragma unroll
            for (int j = 0; j < 4; j++) {
                const int t = ty * 4 + i, u = tx * 4 + j;
                Asc[t][u] = (u <= t) ? acc[i][j] : 0.f;
            }
    }
    __syncthreads();   // scores visible; K reads done -> KVs reusable

    // Load V into KVs; compute denominators in parallel
    for (int i = tid; i < CHUNK * (HD / 4); i += 256) {
        const int t = i >> 4;
        const int d4 = (i & 15) * 4;
        float4 v = *(const float4*)(g_Vb + rowbase + (size_t)t * DD + d4);
        KVs[t][d4] = v.x; KVs[t][d4+1] = v.y; KVs[t][d4+2] = v.z; KVs[t][d4+3] = v.w;
    }
    if (tid < CHUNK) {
        float r = 0.f;
        for (int u = 0; u < CHUNK; u++) r += Asc[tid][u];
        float qz = 0.f;
        for (int d = 0; d < HD; d++) qz = fmaf(Qs[tid][d], zp[d], qz);
        den[tid] = r + qz + 1e-6f;
    }
    __syncthreads();

    // Phase 2: numerator = A @ V + Q @ S_prev ; divide; store
    {
        float o[4][4];
        #pragma unroll
        for (int i = 0; i < 4; i++)
            #pragma unroll
            for (int j = 0; j < 4; j++) o[i][j] = 0.f;
        for (int u = 0; u < CHUNK; u++) {
            float a[4], v[4];
            #pragma unroll
            for (int i = 0; i < 4; i++) { a[i] = Asc[ty * 4 + i][u]; v[i] = KVs[u][tx * 4 + i]; }
            #pragma unroll
            for (int i = 0; i < 4; i++)
                #pragma unroll
                for (int j = 0; j < 4; j++)
                    o[i][j] = fmaf(a[i], v[j], o[i][j]);
        }
        for (int d = 0; d < HD; d++) {
            float q[4], s[4];
            #pragma unroll
            for (int i = 0; i < 4; i++) { q[i] = Qs[ty * 4 + i][d]; s[i] = Ss[d][tx * 4 + i]; }
            #pragma unroll
            for (int i = 0; i < 4; i++)
                #pragma unroll
                for (int j = 0; j < 4; j++)
                    o[i][j] = fmaf(q[i], s[j], o[i][j]);
        }
        #pragma unroll
        for (int i = 0; i < 4; i++) {
            const float inv = 1.0f / den[ty * 4 + i];
            #pragma unroll
            for (int j = 0; j < 4; j++)
                g_VAL[rowbase + (size_t)(ty * 4 + i) * DD + tx * 4 + j] = o[i][j] * inv;
        }
    }
}

// ---------------------------------------------------------------------------
extern "C" void kernel_launch(void* const* d_in, const int* in_sizes, int n_in,
                              void* d_out, int out_size)
{
    (void)in_sizes; (void)n_in; (void)out_size;
    const float* x  = (const float*)d_in[0];
    // d_in[1] = mask (unused, matching reference)
    const float* Wq = (const float*)d_in[2];
    const float* bq = (const float*)d_in[3];
    const float* Wk = (const float*)d_in[4];
    const float* bk = (const float*)d_in[5];
    const float* Wv = (const float*)d_in[6];
    const float* bv = (const float*)d_in[7];
    const float* Wo = (const float*)d_in[8];
    const float* bo = (const float*)d_in[9];
    float* out = (float*)d_out;

    float *pQ, *pK, *pV, *pVAL;
    cudaGetSymbolAddress((void**)&pQ,   g_Q);
    cudaGetSymbolAddress((void**)&pK,   g_Kb);
    cudaGetSymbolAddress((void**)&pV,   g_Vb);
    cudaGetSymbolAddress((void**)&pVAL, g_VAL);

    dim3 ggrid(DD / 128, MTOT / 128);
    gemm_k<1><<<ggrid, 256>>>(x, Wq, bq, pQ, MTOT, DD, DD);  // phi(xWq+bq)
    gemm_k<1><<<ggrid, 256>>>(x, Wk, bk, pK, MTOT, DD, DD);  // phi(xWk+bk)
    gemm_k<0><<<ggrid, 256>>>(x, Wv, bv, pV, MTOT, DD, DD);  // xWv+bv

    dim3 agrid(NCHUNK, NBH);
    kv_chunk_k<<<agrid, 256>>>();
    prefix_k<<<NBH, 1024>>>();

    const int smbytes = (3 * CHUNK * (HD + 1) + CHUNK * (CHUNK + 1) + 2 * CHUNK) * (int)sizeof(float);
    cudaFuncSetAttribute(attn_out_k, cudaFuncAttributeMaxDynamicSharedMemorySize, smbytes);
    attn_out_k<<<agrid, 256, smbytes>>>();

    gemm_k<0><<<ggrid, 256>>>(pVAL, Wo, bo, out, MTOT, DD, DD);  // VAL @ Wo + bo
}

// round 3
// speedup vs baseline: 1.8615x; 1.8615x over previous
#include <cuda_runtime.h>
#include <cuda_bf16.h>
#include <cstdint>

// Problem constants (fixed by reference: B=4, S=2048, D=1024, H=16)
#define DD     1024
#define NH     16
#define HD     64
#define BATCH  4
#define SEQ    2048
#define MTOT   (BATCH * SEQ)      // 8192
#define CHUNK  64
#define NCHUNK (SEQ / CHUNK)      // 32
#define NBH    (BATCH * NH)       // 64

// ---------------- scratch (allocation-free rule: __device__ globals) -------
__device__ float g_Q  [MTOT * DD];
__device__ float g_Kb [MTOT * DD];
__device__ float g_Vb [MTOT * DD];
__device__ float g_VAL[MTOT * DD];
__device__ float g_KV [NBH * NCHUNK * HD * HD];
__device__ float g_KS [NBH * NCHUNK * HD];

__device__ __nv_bfloat16 g_xhi[MTOT * DD];
__device__ __nv_bfloat16 g_xlo[MTOT * DD];
__device__ __nv_bfloat16 g_vhi[MTOT * DD];
__device__ __nv_bfloat16 g_vlo[MTOT * DD];
__device__ __nv_bfloat16 g_wThi[4][DD * DD];   // W^T hi (layout [N][K])
__device__ __nv_bfloat16 g_wTlo[4][DD * DD];   // W^T lo

// ---------------------------------------------------------------------------
// PTX helpers (compute_100-safe: mma.sync / ldmatrix / cp.async only)
// ---------------------------------------------------------------------------
__device__ __forceinline__ uint32_t smem_u32(const void* p) {
    uint32_t a;
    asm("{ .reg .u64 t; cvta.to.shared.u64 t, %1; cvt.u32.u64 %0, t; }" : "=r"(a) : "l"(p));
    return a;
}

#define CP_ASYNC16(dst_u32, src_gptr) \
    asm volatile("cp.async.cg.shared.global [%0], [%1], 16;" \
                 :: "r"(dst_u32), "l"(src_gptr) : "memory")
#define CP_COMMIT() asm volatile("cp.async.commit_group;" ::: "memory")
#define CP_WAIT(n)  asm volatile("cp.async.wait_group %0;" :: "n"(n) : "memory")

#define LDSM_X4(r0, r1, r2, r3, addr) \
    asm volatile("ldmatrix.sync.aligned.m8n8.x4.shared.b16 {%0,%1,%2,%3}, [%4];" \
                 : "=r"(r0), "=r"(r1), "=r"(r2), "=r"(r3) : "r"(addr))

#define MMA16816(d, a, b0v, b1v) \
    asm volatile("mma.sync.aligned.m16n8k16.row.col.f32.bf16.bf16.f32 " \
                 "{%0,%1,%2,%3}, {%4,%5,%6,%7}, {%8,%9}, {%0,%1,%2,%3};" \
                 : "+f"((d)[0]), "+f"((d)[1]), "+f"((d)[2]), "+f"((d)[3]) \
                 : "r"((a)[0]), "r"((a)[1]), "r"((a)[2]), "r"((a)[3]), \
                   "r"(b0v), "r"(b1v))

// ---------------------------------------------------------------------------
// Split fp32 -> (hi, lo) bf16
// ---------------------------------------------------------------------------
__global__ __launch_bounds__(256)
void split_k(const float4* __restrict__ in, uint2* __restrict__ hi,
             uint2* __restrict__ lo, int n4)
{
    int i = blockIdx.x * 256 + threadIdx.x;
    if (i >= n4) return;
    float4 v = in[i];
    __nv_bfloat16 hx = __float2bfloat16_rn(v.x);
    __nv_bfloat16 hy = __float2bfloat16_rn(v.y);
    __nv_bfloat16 hz = __float2bfloat16_rn(v.z);
    __nv_bfloat16 hw = __float2bfloat16_rn(v.w);
    __nv_bfloat16 lx = __float2bfloat16_rn(v.x - __bfloat162float(hx));
    __nv_bfloat16 ly = __float2bfloat16_rn(v.y - __bfloat162float(hy));
    __nv_bfloat16 lz = __float2bfloat16_rn(v.z - __bfloat162float(hz));
    __nv_bfloat16 lw = __float2bfloat16_rn(v.w - __bfloat162float(hw));
    uint2 hp, lp;
    hp.x = ((uint32_t)__bfloat16_as_ushort(hy) << 16) | __bfloat16_as_ushort(hx);
    hp.y = ((uint32_t)__bfloat16_as_ushort(hw) << 16) | __bfloat16_as_ushort(hz);
    lp.x = ((uint32_t)__bfloat16_as_ushort(ly) << 16) | __bfloat16_as_ushort(lx);
    lp.y = ((uint32_t)__bfloat16_as_ushort(lw) << 16) | __bfloat16_as_ushort(lz);
    hi[i] = hp;
    lo[i] = lp;
}

// Transpose + split: W[K][N] fp32 -> hiT/loT[N][K] bf16
__global__ __launch_bounds__(256)
void splitT_k(const float* __restrict__ W, __nv_bfloat16* __restrict__ hiT,
              __nv_bfloat16* __restrict__ loT)
{
    __shared__ float t[32][33];
    const int n0 = blockIdx.x * 32, k0 = blockIdx.y * 32;
    const int tx = threadIdx.x, ty = threadIdx.y;   // 32 x 8
    #pragma unroll
    for (int r = ty; r < 32; r += 8)
        t[r][tx] = W[(size_t)(k0 + r) * DD + n0 + tx];
    __syncthreads();
    #pragma unroll
    for (int r = ty; r < 32; r += 8) {
        float v = t[tx][r];   // = W[k0+tx][n0+r]
        __nv_bfloat16 h = __float2bfloat16_rn(v);
        const size_t o = (size_t)(n0 + r) * DD + k0 + tx;
        hiT[o] = h;
        loT[o] = __float2bfloat16_rn(v - __bfloat162float(h));
    }
}

// ---------------------------------------------------------------------------
// Tensor-core GEMM via mma.sync (bf16 2-term split, fp32 accum):
//   C[M=8192, N=1024] = act(A @ W + bias)
//   A = (Ahi + Alo) [M][K] bf16;  W^T = (BhiT + BloT) [N][K] bf16
//   D += Ahi*Bhi + Ahi*Blo + Alo*Bhi
// CTA tile 128x128, BK=32, 8 warps (warp tile 64x32), cp.async double buffer.
// ---------------------------------------------------------------------------
template<int ACT>
__global__ __launch_bounds__(256, 1)
void tc_gemm_k(const __nv_bfloat16* __restrict__ Ahi, const __nv_bfloat16* __restrict__ Alo,
               const __nv_bfloat16* __restrict__ BhiT, const __nv_bfloat16* __restrict__ BloT,
               const float* __restrict__ bias, float* __restrict__ Cg)
{
    extern __shared__ char smem[];
    const uint32_t sb = smem_u32(smem);
    const int tid = threadIdx.x;
    const int wid = tid >> 5, lane = tid & 31;
    const int n0 = blockIdx.x * 128, m0 = blockIdx.y * 128;
    const int wm = wid & 1;        // 0/1 -> M half (64 rows)
    const int wn = wid >> 1;       // 0..3 -> 32-col slab

    constexpr int SROWB  = 80;            // padded bytes per smem row (64B data + 16B pad)
    constexpr int TILEB  = 128 * SROWB;   // 10240 B per tile
    constexpr int STAGEB = 4 * TILEB;     // Ahi, Alo, Bhi, Blo
    constexpr int NIT    = DD / 32;       // 32 k-iterations

    const uint64_t gAh = __cvta_generic_to_global(Ahi);
    const uint64_t gAl = __cvta_generic_to_global(Alo);
    const uint64_t gBh = __cvta_generic_to_global(BhiT);
    const uint64_t gBl = __cvta_generic_to_global(BloT);

    float acc[4][4][4];
    #pragma unroll
    for (int i = 0; i < 4; i++)
        #pragma unroll
        for (int j = 0; j < 4; j++)
            #pragma unroll
            for (int q = 0; q < 4; q++) acc[i][j][q] = 0.f;

    // per-thread load coords (2 chunks of 16B per tile per stage)
    const int c0row = tid >> 2, c0k = (tid & 3);
    const int c1row = (tid + 256) >> 2, c1k = ((tid + 256) & 3);

    auto load_stage = [&](int stage, int kc) {
        const uint32_t sbase = sb + stage * STAGEB;
        {
            const uint32_t doff = c0row * SROWB + c0k * 16;
            const uint64_t oa = ((size_t)(m0 + c0row) * DD + kc + c0k * 8) * 2;
            const uint64_t ob = ((size_t)(n0 + c0row) * DD + kc + c0k * 8) * 2;
            CP_ASYNC16(sbase + 0 * TILEB + doff, gAh + oa);
            CP_ASYNC16(sbase + 1 * TILEB + doff, gAl + oa);
            CP_ASYNC16(sbase + 2 * TILEB + doff, gBh + ob);
            CP_ASYNC16(sbase + 3 * TILEB + doff, gBl + ob);
        }
        {
            const uint32_t doff = c1row * SROWB + c1k * 16;
            const uint64_t oa = ((size_t)(m0 + c1row) * DD + kc + c1k * 8) * 2;
            const uint64_t ob = ((size_t)(n0 + c1row) * DD + kc + c1k * 8) * 2;
            CP_ASYNC16(sbase + 0 * TILEB + doff, gAh + oa);
            CP_ASYNC16(sbase + 1 * TILEB + doff, gAl + oa);
            CP_ASYNC16(sbase + 2 * TILEB + doff, gBh + ob);
            CP_ASYNC16(sbase + 3 * TILEB + doff, gBl + ob);
        }
    };

    // ldmatrix per-lane base offsets (bytes within a tile)
    // A fragment (m16 x k16): row = wm*64 + mf*16 + (lane&15); k-half = lane>>4
    const uint32_t aOff = (uint32_t)(wm * 64 + (lane & 15)) * SROWB + (uint32_t)(lane >> 4) * 16;
    // B fragment (n16 x k16): n = wn*32 + g*16 + (lane&7) + ((lane>>4)<<3); k-half = (lane>>3)&1
    const uint32_t bOff = (uint32_t)(wn * 32 + (lane & 7) + ((lane >> 4) << 3)) * SROWB
                        + (uint32_t)((lane >> 3) & 1) * 16;

    load_stage(0, 0);  CP_COMMIT();
    load_stage(1, 32); CP_COMMIT();

    for (int it = 0; it < NIT; it++) {
        if (it + 1 < NIT) { CP_WAIT(1); } else { CP_WAIT(0); }
        __syncthreads();

        const uint32_t sA_hi = sb + (it & 1) * STAGEB;
        const uint32_t sA_lo = sA_hi + TILEB;
        const uint32_t sB_hi = sA_hi + 2 * TILEB;
        const uint32_t sB_lo = sA_hi + 3 * TILEB;

        #pragma unroll
        for (int k16 = 0; k16 < 2; k16++) {
            const uint32_t kb = k16 * 32;   // 16 bf16 = 32 bytes
            uint32_t ah[4][4], al[4][4];
            #pragma unroll
            for (int mf = 0; mf < 4; mf++) {
                const uint32_t ao = aOff + mf * 16 * SROWB + kb;
                LDSM_X4(ah[mf][0], ah[mf][1], ah[mf][2], ah[mf][3], sA_hi + ao);
                LDSM_X4(al[mf][0], al[mf][1], al[mf][2], al[mf][3], sA_lo + ao);
            }
            uint32_t bh[2][4], bl[2][4];
            #pragma unroll
            for (int g = 0; g < 2; g++) {
                const uint32_t bo = bOff + g * 16 * SROWB + kb;
                LDSM_X4(bh[g][0], bh[g][1], bh[g][2], bh[g][3], sB_hi + bo);
                LDSM_X4(bl[g][0], bl[g][1], bl[g][2], bl[g][3], sB_lo + bo);
            }
            #pragma unroll
            for (int mf = 0; mf < 4; mf++) {
                #pragma unroll
                for (int nf = 0; nf < 4; nf++) {
                    const int g = nf >> 1, p = (nf & 1) * 2;
                    MMA16816(acc[mf][nf], ah[mf], bh[g][p], bh[g][p + 1]);   // hi*hi
                    MMA16816(acc[mf][nf], ah[mf], bl[g][p], bl[g][p + 1]);   // hi*lo
                    MMA16816(acc[mf][nf], al[mf], bh[g][p], bh[g][p + 1]);   // lo*hi
                }
            }
        }
        __syncthreads();
        if (it + 2 < NIT) { load_stage(it & 1, (it + 2) * 32); CP_COMMIT(); }
    }

    // epilogue: bias + optional elu(x)+1, fp32 stores
    #pragma unroll
    for (int nf = 0; nf < 4; nf++) {
        const int cg = n0 + wn * 32 + nf * 8 + (lane & 3) * 2;
        const float b0 = __ldg(&bias[cg]);
        const float b1 = __ldg(&bias[cg + 1]);
        #pragma unroll
        for (int mf = 0; mf < 4; mf++) {
            const int rg = m0 + wm * 64 + mf * 16 + (lane >> 2);
            float v0 = acc[mf][nf][0] + b0;
            float v1 = acc[mf][nf][1] + b1;
            float v2 = acc[mf][nf][2] + b0;
            float v3 = acc[mf][nf][3] + b1;
            if (ACT) {
                v0 = (v0 > 0.f) ? (v0 + 1.f) : __expf(v0);
                v1 = (v1 > 0.f) ? (v1 + 1.f) : __expf(v1);
                v2 = (v2 > 0.f) ? (v2 + 1.f) : __expf(v2);
                v3 = (v3 > 0.f) ? (v3 + 1.f) : __expf(v3);
            }
            *(float2*)(Cg + (size_t)rg * DD + cg)       = make_float2(v0, v1);
            *(float2*)(Cg + (size_t)(rg + 8) * DD + cg) = make_float2(v2, v3);
        }
    }
}

// ---------------------------------------------------------------------------
// Pass A: per (bh, chunk): KV_c[d][m] = sum_t K[t][d]*V[t][m];  ks_c[d]=sum_t K[t][d]
// ---------------------------------------------------------------------------
__global__ __launch_bounds__(256)
void kv_chunk_k()
{
    const int c = blockIdx.x, bh = blockIdx.y;
    const int b = bh >> 4, h = bh & 15;
    __shared__ float Ks[CHUNK][HD + 1];
    __shared__ float Vs[CHUNK][HD + 1];
    const int tid = threadIdx.x;
    const size_t rowbase = (size_t)(b * SEQ + c * CHUNK) * DD + h * HD;

    for (int i = tid; i < CHUNK * (HD / 4); i += 256) {
        const int t = i >> 4;
        const int d4 = (i & 15) * 4;
        float4 kq = *(const float4*)(g_Kb + rowbase + (size_t)t * DD + d4);
        Ks[t][d4] = kq.x; Ks[t][d4+1] = kq.y; Ks[t][d4+2] = kq.z; Ks[t][d4+3] = kq.w;
        float4 vq = *(const float4*)(g_Vb + rowbase + (size_t)t * DD + d4);
        Vs[t][d4] = vq.x; Vs[t][d4+1] = vq.y; Vs[t][d4+2] = vq.z; Vs[t][d4+3] = vq.w;
    }
    __syncthreads();

    const int ty = tid >> 4, tx = tid & 15;
    float acc[4][4];
    #pragma unroll
    for (int i = 0; i < 4; i++)
        #pragma unroll
        for (int j = 0; j < 4; j++) acc[i][j] = 0.f;

    for (int t = 0; t < CHUNK; t++) {
        float kr[4], vr[4];
        #pragma unroll
        for (int i = 0; i < 4; i++) { kr[i] = Ks[t][ty * 4 + i]; vr[i] = Vs[t][tx * 4 + i]; }
        #pragma unroll
        for (int i = 0; i < 4; i++)
            #pragma unroll
            for (int j = 0; j < 4; j++)
                acc[i][j] = fmaf(kr[i], vr[j], acc[i][j]);
    }

    float* outp = g_KV + (size_t)(bh * NCHUNK + c) * HD * HD;
    #pragma unroll
    for (int i = 0; i < 4; i++)
        #pragma unroll
        for (int j = 0; j < 4; j++)
            outp[(ty * 4 + i) * HD + tx * 4 + j] = acc[i][j];

    if (tid < HD) {
        float s = 0.f;
        for (int t = 0; t < CHUNK; t++) s += Ks[t][tid];
        g_KS[(bh * NCHUNK + c) * HD + tid] = s;
    }
}

// ---------------------------------------------------------------------------
// Pass B: in-place EXCLUSIVE prefix over chunks (per bh)
// ---------------------------------------------------------------------------
__global__ __launch_bounds__(1024)
void prefix_k()
{
    const int bh = blockIdx.x;
    const int tid = threadIdx.x;
    float4 run = make_float4(0.f, 0.f, 0.f, 0.f);
    float* base = g_KV + (size_t)bh * NCHUNK * HD * HD;
    for (int c = 0; c < NCHUNK; c++) {
        float4* p = (float4*)(base + (size_t)c * HD * HD) + tid;
        float4 v = *p;
        *p = run;
        run.x += v.x; run.y += v.y; run.z += v.z; run.w += v.w;
    }
    if (tid < HD) {
        float r = 0.f;
        float* zb = g_KS + (size_t)bh * NCHUNK * HD + tid;
        for (int c = 0; c < NCHUNK; c++) { float v = zb[(size_t)c * HD]; zb[(size_t)c * HD] = r; r += v; }
    }
}

// ---------------------------------------------------------------------------
// Pass C: per (bh, chunk): out = (tril(QK^T) V + Q S_prev) / (rowsum + Q.z_prev + eps)
// ---------------------------------------------------------------------------
__global__ __launch_bounds__(256)
void attn_out_k()
{
    extern __shared__ float sm[];
    float (*Qs) [HD + 1]    = (float(*)[HD + 1])sm;
    float (*KVs)[HD + 1]    = (float(*)[HD + 1])(sm + CHUNK * (HD + 1));
    float (*Ss) [HD + 1]    = (float(*)[HD + 1])(sm + 2 * CHUNK * (HD + 1));
    float (*Asc)[CHUNK + 1] = (float(*)[CHUNK + 1])(sm + 3 * CHUNK * (HD + 1));
    float* den = sm + 3 * CHUNK * (HD + 1) + CHUNK * (CHUNK + 1);
    float* zp  = den + CHUNK;

    const int c = blockIdx.x, bh = blockIdx.y;
    const int b = bh >> 4, h = bh & 15;
    const int tid = threadIdx.x;
    const size_t rowbase = (size_t)(b * SEQ + c * CHUNK) * DD + h * HD;
    const float* Sp = g_KV + (size_t)(bh * NCHUNK + c) * HD * HD;

    for (int i = tid; i < CHUNK * (HD / 4); i += 256) {
        const int t = i >> 4;
        const int d4 = (i & 15) * 4;
        float4 q = *(const float4*)(g_Q  + rowbase + (size_t)t * DD + d4);
        Qs[t][d4] = q.x; Qs[t][d4+1] = q.y; Qs[t][d4+2] = q.z; Qs[t][d4+3] = q.w;
        float4 k = *(const float4*)(g_Kb + rowbase + (size_t)t * DD + d4);
        KVs[t][d4] = k.x; KVs[t][d4+1] = k.y; KVs[t][d4+2] = k.z; KVs[t][d4+3] = k.w;
        float4 s = *(const float4*)(Sp + (size_t)t * HD + d4);
        Ss[t][d4] = s.x; Ss[t][d4+1] = s.y; Ss[t][d4+2] = s.z; Ss[t][d4+3] = s.w;
    }
    if (tid < HD) zp[tid] = g_KS[(bh * NCHUNK + c) * HD + tid];
    __syncthreads();

    const int ty = tid >> 4, tx = tid & 15;

    {
        float acc[4][4];
        #pragma unroll
        for (int i = 0; i < 4; i++)
            #pragma unroll
            for (int j = 0; j < 4; j++) acc[i][j] = 0.f;
        for (int d = 0; d < HD; d++) {
            float q[4], k[4];
            #pragma unroll
            for (int i = 0; i < 4; i++) { q[i] = Qs[ty * 4 + i][d]; k[i] = KVs[tx * 4 + i][d]; }
            #pragma unroll
            for (int i = 0; i < 4; i++)
                #pragma unroll
                for (int j = 0; j < 4; j++)
                    acc[i][j] = fmaf(q[i], k[j], acc[i][j]);
        }
        #pragma unroll
        for (int i = 0; i < 4; i++)
            #pragma unroll
            for (int j = 0; j < 4; j++) {
                const int t = ty * 4 + i, u = tx * 4 + j;
                Asc[t][u] = (u <= t) ? acc[i][j] : 0.f;
            }
    }
    __syncthreads();

    for (int i = tid; i < CHUNK * (HD / 4); i += 256) {
        const int t = i >> 4;
        const int d4 = (i & 15) * 4;
        float4 v = *(const float4*)(g_Vb + rowbase + (size_t)t * DD + d4);
        KVs[t][d4] = v.x; KVs[t][d4+1] = v.y; KVs[t][d4+2] = v.z; KVs[t][d4+3] = v.w;
    }
    if (tid < CHUNK) {
        float r = 0.f;
        for (int u = 0; u < CHUNK; u++) r += Asc[tid][u];
        float qz = 0.f;
        for (int d = 0; d < HD; d++) qz = fmaf(Qs[tid][d], zp[d], qz);
        den[tid] = r + qz + 1e-6f;
    }
    __syncthreads();

    {
        float o[4][4];
        #pragma unroll
        for (int i = 0; i < 4; i++)
            #pragma unroll
            for (int j = 0; j < 4; j++) o[i][j] = 0.f;
        for (int u = 0; u < CHUNK; u++) {
            float a[4], v[4];
            #pragma unroll
            for (int i = 0; i < 4; i++) { a[i] = Asc[ty * 4 + i][u]; v[i] = KVs[u][tx * 4 + i]; }
            #pragma unroll
            for (int i = 0; i < 4; i++)
                #pragma unroll
                for (int j = 0; j < 4; j++)
                    o[i][j] = fmaf(a[i], v[j], o[i][j]);
        }
        for (int d = 0; d < HD; d++) {
            float q[4], s[4];
            #pragma unroll
            for (int i = 0; i < 4; i++) { q[i] = Qs[ty * 4 + i][d]; s[i] = Ss[d][tx * 4 + i]; }
            #pragma unroll
            for (int i = 0; i < 4; i++)
                #pragma unroll
                for (int j = 0; j < 4; j++)
                    o[i][j] = fmaf(q[i], s[j], o[i][j]);
        }
        #pragma unroll
        for (int i = 0; i < 4; i++) {
            const float inv = 1.0f / den[ty * 4 + i];
            #pragma unroll
            for (int j = 0; j < 4; j++)
                g_VAL[rowbase + (size_t)(ty * 4 + i) * DD + tx * 4 + j] = o[i][j] * inv;
        }
    }
}

// ---------------------------------------------------------------------------
extern "C" void kernel_launch(void* const* d_in, const int* in_sizes, int n_in,
                              void* d_out, int out_size)
{
    (void)in_sizes; (void)n_in; (void)out_size;
    const float* x  = (const float*)d_in[0];
    const float* Wq = (const float*)d_in[2];
    const float* bq = (const float*)d_in[3];
    const float* Wk = (const float*)d_in[4];
    const float* bk = (const float*)d_in[5];
    const float* Wv = (const float*)d_in[6];
    const float* bv = (const float*)d_in[7];
    const float* Wo = (const float*)d_in[8];
    const float* bo = (const float*)d_in[9];
    float* out = (float*)d_out;

    float *pQ, *pK, *pV, *pVAL;
    __nv_bfloat16 *pxh, *pxl, *pvh, *pvl, *pwh, *pwl;
    cudaGetSymbolAddress((void**)&pQ,   g_Q);
    cudaGetSymbolAddress((void**)&pK,   g_Kb);
    cudaGetSymbolAddress((void**)&pV,   g_Vb);
    cudaGetSymbolAddress((void**)&pVAL, g_VAL);
    cudaGetSymbolAddress((void**)&pxh,  g_xhi);
    cudaGetSymbolAddress((void**)&pxl,  g_xlo);
    cudaGetSymbolAddress((void**)&pvh,  g_vhi);
    cudaGetSymbolAddress((void**)&pvl,  g_vlo);
    cudaGetSymbolAddress((void**)&pwh,  g_wThi);
    cudaGetSymbolAddress((void**)&pwl,  g_wTlo);

    const int smbytes_g = 2 * 4 * 128 * 80;   // 81920
    cudaFuncSetAttribute(tc_gemm_k<0>, cudaFuncAttributeMaxDynamicSharedMemorySize, smbytes_g);
    cudaFuncSetAttribute(tc_gemm_k<1>, cudaFuncAttributeMaxDynamicSharedMemorySize, smbytes_g);

    // split inputs
    const int n4 = MTOT * DD / 4;
    split_k<<<(n4 + 255) / 256, 256>>>((const float4*)x, (uint2*)pxh, (uint2*)pxl, n4);
    dim3 tgrid(DD / 32, DD / 32), tblk(32, 8);
    splitT_k<<<tgrid, tblk>>>(Wq, pwh + 0 * (size_t)DD * DD, pwl + 0 * (size_t)DD * DD);
    splitT_k<<<tgrid, tblk>>>(Wk, pwh + 1 * (size_t)DD * DD, pwl + 1 * (size_t)DD * DD);
    splitT_k<<<tgrid, tblk>>>(Wv, pwh + 2 * (size_t)DD * DD, pwl + 2 * (size_t)DD * DD);
    splitT_k<<<tgrid, tblk>>>(Wo, pwh + 3 * (size_t)DD * DD, pwl + 3 * (size_t)DD * DD);

    // projections on tensor cores (mma.sync)
    dim3 ggrid(DD / 128, MTOT / 128);
    tc_gemm_k<1><<<ggrid, 256, smbytes_g>>>(pxh, pxl, pwh + 0 * (size_t)DD * DD, pwl + 0 * (size_t)DD * DD, bq, pQ);
    tc_gemm_k<1><<<ggrid, 256, smbytes_g>>>(pxh, pxl, pwh + 1 * (size_t)DD * DD, pwl + 1 * (size_t)DD * DD, bk, pK);
    tc_gemm_k<0><<<ggrid, 256, smbytes_g>>>(pxh, pxl, pwh + 2 * (size_t)DD * DD, pwl + 2 * (size_t)DD * DD, bv, pV);

    // linear attention (fp32)
    dim3 agrid(NCHUNK, NBH);
    kv_chunk_k<<<agrid, 256>>>();
    prefix_k<<<NBH, 1024>>>();
    const int smbytes_a = (3 * CHUNK * (HD + 1) + CHUNK * (CHUNK + 1) + 2 * CHUNK) * (int)sizeof(float);
    cudaFuncSetAttribute(attn_out_k, cudaFuncAttributeMaxDynamicSharedMemorySize, smbytes_a);
    attn_out_k<<<agrid, 256, smbytes_a>>>();

    // output projection
    split_k<<<(n4 + 255) / 256, 256>>>((const float4*)pVAL, (uint2*)pvh, (uint2*)pvl, n4);
    tc_gemm_k<0><<<ggrid, 256, smbytes_g>>>(pvh, pvl, pwh + 3 * (size_t)DD * DD, pwl + 3 * (size_t)DD * DD, bo, out);
}

// round 4
// speedup vs baseline: 3.2708x; 1.7571x over previous
#include <cuda_runtime.h>
#include <cuda_fp16.h>
#include <cstdint>

// Problem constants (fixed by reference: B=4, S=2048, D=1024, H=16)
#define DD     1024
#define NH     16
#define HD     64
#define BATCH  4
#define SEQ    2048
#define MTOT   (BATCH * SEQ)      // 8192
#define CHUNK  64
#define NCHUNK (SEQ / CHUNK)      // 32
#define NBH    (BATCH * NH)       // 64

// ---------------- scratch (allocation-free rule: __device__ globals) -------
__device__ float g_KV [NBH * NCHUNK * HD * HD];
__device__ float g_KS [NBH * NCHUNK * HD];

__device__ __half g_xh  [MTOT * DD];     // x in fp16
__device__ __half g_qh  [MTOT * DD];     // phi(xWq+b)
__device__ __half g_kh  [MTOT * DD];     // phi(xWk+b)
__device__ __half g_vh  [MTOT * DD];     // xWv+b
__device__ __half g_valh[MTOT * DD];     // attention output (fp16)
__device__ __half g_wT  [4][DD * DD];    // W^T fp16 (layout [N][K])

// ---------------------------------------------------------------------------
// PTX helpers (compute_100-safe: mma.sync / ldmatrix / cp.async only)
// ---------------------------------------------------------------------------
__device__ __forceinline__ uint32_t smem_u32(const void* p) {
    uint32_t a;
    asm("{ .reg .u64 t; cvta.to.shared.u64 t, %1; cvt.u32.u64 %0, t; }" : "=r"(a) : "l"(p));
    return a;
}

#define CP_ASYNC16(dst_u32, src_gptr) \
    asm volatile("cp.async.cg.shared.global [%0], [%1], 16;" \
                 :: "r"(dst_u32), "l"(src_gptr) : "memory")
#define CP_COMMIT() asm volatile("cp.async.commit_group;" ::: "memory")
#define CP_WAIT(n)  asm volatile("cp.async.wait_group %0;" :: "n"(n) : "memory")

#define LDSM_X4(r0, r1, r2, r3, addr) \
    asm volatile("ldmatrix.sync.aligned.m8n8.x4.shared.b16 {%0,%1,%2,%3}, [%4];" \
                 : "=r"(r0), "=r"(r1), "=r"(r2), "=r"(r3) : "r"(addr))

#define MMA16816F16(d, a, b0v, b1v) \
    asm volatile("mma.sync.aligned.m16n8k16.row.col.f32.f16.f16.f32 " \
                 "{%0,%1,%2,%3}, {%4,%5,%6,%7}, {%8,%9}, {%0,%1,%2,%3};" \
                 : "+f"((d)[0]), "+f"((d)[1]), "+f"((d)[2]), "+f"((d)[3]) \
                 : "r"((a)[0]), "r"((a)[1]), "r"((a)[2]), "r"((a)[3]), \
                   "r"(b0v), "r"(b1v))

// unpack 8 fp16 (uint4) -> 8 contiguous floats
__device__ __forceinline__ void put8(float* dst, uint4 r) {
    const __half2* hp = (const __half2*)&r;
    #pragma unroll
    for (int q = 0; q < 4; q++) {
        float2 f = __half22float2(hp[q]);
        dst[2 * q] = f.x; dst[2 * q + 1] = f.y;
    }
}

// ---------------------------------------------------------------------------
// fp32 -> fp16 (vectorized)
// ---------------------------------------------------------------------------
__global__ __launch_bounds__(256)
void convh_k(const float4* __restrict__ in, uint2* __restrict__ out, int n4)
{
    int i = blockIdx.x * 256 + threadIdx.x;
    if (i >= n4) return;
    float4 v = in[i];
    __half2 a = __floats2half2_rn(v.x, v.y);
    __half2 b = __floats2half2_rn(v.z, v.w);
    uint2 o;
    o.x = *(uint32_t*)&a;
    o.y = *(uint32_t*)&b;
    out[i] = o;
}

// Transpose + convert: W[K][N] fp32 -> wT[N][K] fp16
__global__ __launch_bounds__(256)
void convT_k(const float* __restrict__ W, __half* __restrict__ hT)
{
    __shared__ float t[32][33];
    const int n0 = blockIdx.x * 32, k0 = blockIdx.y * 32;
    const int tx = threadIdx.x, ty = threadIdx.y;   // 32 x 8
    #pragma unroll
    for (int r = ty; r < 32; r += 8)
        t[r][tx] = W[(size_t)(k0 + r) * DD + n0 + tx];
    __syncthreads();
    #pragma unroll
    for (int r = ty; r < 32; r += 8)
        hT[(size_t)(n0 + r) * DD + k0 + tx] = __float2half_rn(t[tx][r]);
}

// ---------------------------------------------------------------------------
// fp16 tensor-core GEMM: C[M=8192, N=1024] = act(A @ W + bias)
//   A fp16 [M][K];  W^T fp16 [N][K];  fp32 accumulate.
// CTA tile 128x128, BK=32, 8 warps (warp tile 64x32), 3-stage cp.async.
//   HALF_OUT=1 -> fp16 C;  HALF_OUT=0 -> fp32 C.
// ---------------------------------------------------------------------------
template<int ACT, int HALF_OUT>
__global__ __launch_bounds__(256, 1)
void tc_gemm_k(const __half* __restrict__ A, const __half* __restrict__ BT,
               const float* __restrict__ bias, void* __restrict__ Cg)
{
    extern __shared__ char smem[];
    const uint32_t sb = smem_u32(smem);
    const int tid = threadIdx.x;
    const int wid = tid >> 5, lane = tid & 31;
    const int n0 = blockIdx.x * 128, m0 = blockIdx.y * 128;
    const int wm = wid & 1;        // M half (64 rows)
    const int wn = wid >> 1;       // 32-col slab

    constexpr int SROWB  = 80;            // 64B data + 16B pad per smem row
    constexpr int TILEB  = 128 * SROWB;   // 10240 B
    constexpr int STAGEB = 2 * TILEB;     // A + B
    constexpr int NIT    = DD / 32;       // 32

    const uint64_t gA = __cvta_generic_to_global(A);
    const uint64_t gB = __cvta_generic_to_global(BT);

    float acc[4][4][4];
    #pragma unroll
    for (int i = 0; i < 4; i++)
        #pragma unroll
        for (int j = 0; j < 4; j++)
            #pragma unroll
            for (int q = 0; q < 4; q++) acc[i][j][q] = 0.f;

    const int c0row = tid >> 2,        c0k = tid & 3;
    const int c1row = (tid + 256) >> 2, c1k = (tid + 256) & 3;

    auto load_stage = [&](int slot, int kc) {
        const uint32_t sbase = sb + slot * STAGEB;
        {
            const uint32_t doff = c0row * SROWB + c0k * 16;
            const uint64_t oa = ((size_t)(m0 + c0row) * DD + kc + c0k * 8) * 2;
            const uint64_t ob = ((size_t)(n0 + c0row) * DD + kc + c0k * 8) * 2;
            CP_ASYNC16(sbase + doff, gA + oa);
            CP_ASYNC16(sbase + TILEB + doff, gB + ob);
        }
        {
            const uint32_t doff = c1row * SROWB + c1k * 16;
            const uint64_t oa = ((size_t)(m0 + c1row) * DD + kc + c1k * 8) * 2;
            const uint64_t ob = ((size_t)(n0 + c1row) * DD + kc + c1k * 8) * 2;
            CP_ASYNC16(sbase + doff, gA + oa);
            CP_ASYNC16(sbase + TILEB + doff, gB + ob);
        }
    };

    // ldmatrix per-lane base offsets (bytes within a tile)
    const uint32_t aOff = (uint32_t)(wm * 64 + (lane & 15)) * SROWB + (uint32_t)(lane >> 4) * 16;
    const uint32_t bOff = (uint32_t)(wn * 32 + (lane & 7) + ((lane >> 4) << 3)) * SROWB
                        + (uint32_t)((lane >> 3) & 1) * 16;

    load_stage(0, 0);  CP_COMMIT();
    load_stage(1, 32); CP_COMMIT();
    load_stage(2, 64); CP_COMMIT();

    for (int it = 0; it < NIT; it++) {
        if (it < NIT - 2)      { CP_WAIT(2); }
        else if (it == NIT - 2){ CP_WAIT(1); }
        else                   { CP_WAIT(0); }
        __syncthreads();

        const int slot = it % 3;
        const uint32_t sA = sb + slot * STAGEB;
        const uint32_t sB = sA + TILEB;

        #pragma unroll
        for (int k16 = 0; k16 < 2; k16++) {
            const uint32_t kb = k16 * 32;   // 16 fp16 = 32 bytes
            uint32_t ah[4][4];
            #pragma unroll
            for (int mf = 0; mf < 4; mf++) {
                const uint32_t ao = aOff + mf * 16 * SROWB + kb;
                LDSM_X4(ah[mf][0], ah[mf][1], ah[mf][2], ah[mf][3], sA + ao);
            }
            uint32_t bb[2][4];
            #pragma unroll
            for (int g = 0; g < 2; g++) {
                const uint32_t bo = bOff + g * 16 * SROWB + kb;
                LDSM_X4(bb[g][0], bb[g][1], bb[g][2], bb[g][3], sB + bo);
            }
            #pragma unroll
            for (int mf = 0; mf < 4; mf++) {
                #pragma unroll
                for (int nf = 0; nf < 4; nf++) {
                    const int g = nf >> 1, p = (nf & 1) * 2;
                    MMA16816F16(acc[mf][nf], ah[mf], bb[g][p], bb[g][p + 1]);
                }
            }
        }
        __syncthreads();
        if (it + 3 < NIT) { load_stage(slot, (it + 3) * 32); CP_COMMIT(); }
    }

    // epilogue: bias + optional elu(x)+1
    #pragma unroll
    for (int nf = 0; nf < 4; nf++) {
        const int cg = n0 + wn * 32 + nf * 8 + (lane & 3) * 2;
        const float b0 = __ldg(&bias[cg]);
        const float b1 = __ldg(&bias[cg + 1]);
        #pragma unroll
        for (int mf = 0; mf < 4; mf++) {
            const int rg = m0 + wm * 64 + mf * 16 + (lane >> 2);
            float v0 = acc[mf][nf][0] + b0;
            float v1 = acc[mf][nf][1] + b1;
            float v2 = acc[mf][nf][2] + b0;
            float v3 = acc[mf][nf][3] + b1;
            if (ACT) {
                v0 = (v0 > 0.f) ? (v0 + 1.f) : __expf(v0);
                v1 = (v1 > 0.f) ? (v1 + 1.f) : __expf(v1);
                v2 = (v2 > 0.f) ? (v2 + 1.f) : __expf(v2);
                v3 = (v3 > 0.f) ? (v3 + 1.f) : __expf(v3);
            }
            if (HALF_OUT) {
                __half* Ch = (__half*)Cg;
                *(__half2*)(Ch + (size_t)rg * DD + cg)       = __floats2half2_rn(v0, v1);
                *(__half2*)(Ch + (size_t)(rg + 8) * DD + cg) = __floats2half2_rn(v2, v3);
            } else {
                float* Cf = (float*)Cg;
                *(float2*)(Cf + (size_t)rg * DD + cg)       = make_float2(v0, v1);
                *(float2*)(Cf + (size_t)(rg + 8) * DD + cg) = make_float2(v2, v3);
            }
        }
    }
}

// ---------------------------------------------------------------------------
// Pass A: per (bh, chunk): KV_c[d][m] = sum_t K[t][d]*V[t][m];  ks_c[d]=sum_t K[t][d]
// ---------------------------------------------------------------------------
__global__ __launch_bounds__(256)
void kv_chunk_k()
{
    const int c = blockIdx.x, bh = blockIdx.y;
    const int b = bh >> 4, h = bh & 15;
    __shared__ float Ks[CHUNK][HD + 1];
    __shared__ float Vs[CHUNK][HD + 1];
    const int tid = threadIdx.x;
    const size_t rowbase = (size_t)(b * SEQ + c * CHUNK) * DD + h * HD;

    for (int i = tid; i < CHUNK * (HD / 8); i += 256) {
        const int t = i >> 3;
        const int d8 = (i & 7) * 8;
        put8(&Ks[t][d8], *(const uint4*)(g_kh + rowbase + (size_t)t * DD + d8));
        put8(&Vs[t][d8], *(const uint4*)(g_vh + rowbase + (size_t)t * DD + d8));
    }
    __syncthreads();

    const int ty = tid >> 4, tx = tid & 15;
    float acc[4][4];
    #pragma unroll
    for (int i = 0; i < 4; i++)
        #pragma unroll
        for (int j = 0; j < 4; j++) acc[i][j] = 0.f;

    for (int t = 0; t < CHUNK; t++) {
        float kr[4], vr[4];
        #pragma unroll
        for (int i = 0; i < 4; i++) { kr[i] = Ks[t][ty * 4 + i]; vr[i] = Vs[t][tx * 4 + i]; }
        #pragma unroll
        for (int i = 0; i < 4; i++)
            #pragma unroll
            for (int j = 0; j < 4; j++)
                acc[i][j] = fmaf(kr[i], vr[j], acc[i][j]);
    }

    float* outp = g_KV + (size_t)(bh * NCHUNK + c) * HD * HD;
    #pragma unroll
    for (int i = 0; i < 4; i++)
        #pragma unroll
        for (int j = 0; j < 4; j++)
            outp[(ty * 4 + i) * HD + tx * 4 + j] = acc[i][j];

    if (tid < HD) {
        float s = 0.f;
        for (int t = 0; t < CHUNK; t++) s += Ks[t][tid];
        g_KS[(bh * NCHUNK + c) * HD + tid] = s;
    }
}

// ---------------------------------------------------------------------------
// Pass B: in-place EXCLUSIVE prefix over chunks (per bh)
// ---------------------------------------------------------------------------
__global__ __launch_bounds__(1024)
void prefix_k()
{
    const int bh = blockIdx.x;
    const int tid = threadIdx.x;
    float4 run = make_float4(0.f, 0.f, 0.f, 0.f);
    float* base = g_KV + (size_t)bh * NCHUNK * HD * HD;
    for (int c = 0; c < NCHUNK; c++) {
        float4* p = (float4*)(base + (size_t)c * HD * HD) + tid;
        float4 v = *p;
        *p = run;
        run.x += v.x; run.y += v.y; run.z += v.z; run.w += v.w;
    }
    if (tid < HD) {
        float r = 0.f;
        float* zb = g_KS + (size_t)bh * NCHUNK * HD + tid;
        for (int c = 0; c < NCHUNK; c++) { float v = zb[(size_t)c * HD]; zb[(size_t)c * HD] = r; r += v; }
    }
}

// ---------------------------------------------------------------------------
// Pass C: per (bh, chunk): out = (tril(QK^T) V + Q S_prev) / (rowsum + Q.z_prev + eps)
// Reads fp16 Q/K/V, fp32 state; writes fp16 VAL.
// ---------------------------------------------------------------------------
__global__ __launch_bounds__(256)
void attn_out_k()
{
    extern __shared__ float sm[];
    float (*Qs) [HD + 1]    = (float(*)[HD + 1])sm;
    float (*KVs)[HD + 1]    = (float(*)[HD + 1])(sm + CHUNK * (HD + 1));
    float (*Ss) [HD + 1]    = (float(*)[HD + 1])(sm + 2 * CHUNK * (HD + 1));
    float (*Asc)[CHUNK + 1] = (float(*)[CHUNK + 1])(sm + 3 * CHUNK * (HD + 1));
    float* den = sm + 3 * CHUNK * (HD + 1) + CHUNK * (CHUNK + 1);
    float* zp  = den + CHUNK;

    const int c = blockIdx.x, bh = blockIdx.y;
    const int b = bh >> 4, h = bh & 15;
    const int tid = threadIdx.x;
    const size_t rowbase = (size_t)(b * SEQ + c * CHUNK) * DD + h * HD;
    const float* Sp = g_KV + (size_t)(bh * NCHUNK + c) * HD * HD;

    for (int i = tid; i < CHUNK * (HD / 8); i += 256) {
        const int t = i >> 3;
        const int d8 = (i & 7) * 8;
        put8(&Qs[t][d8],  *(const uint4*)(g_qh + rowbase + (size_t)t * DD + d8));
        put8(&KVs[t][d8], *(const uint4*)(g_kh + rowbase + (size_t)t * DD + d8));
        float4 s0 = *(const float4*)(Sp + (size_t)t * HD + d8);
        float4 s1 = *(const float4*)(Sp + (size_t)t * HD + d8 + 4);
        Ss[t][d8+0] = s0.x; Ss[t][d8+1] = s0.y; Ss[t][d8+2] = s0.z; Ss[t][d8+3] = s0.w;
        Ss[t][d8+4] = s1.x; Ss[t][d8+5] = s1.y; Ss[t][d8+6] = s1.z; Ss[t][d8+7] = s1.w;
    }
    if (tid < HD) zp[tid] = g_KS[(bh * NCHUNK + c) * HD + tid];
    __syncthreads();

    const int ty = tid >> 4, tx = tid & 15;

    // Phase 1: masked scores
    {
        float acc[4][4];
        #pragma unroll
        for (int i = 0; i < 4; i++)
            #pragma unroll
            for (int j = 0; j < 4; j++) acc[i][j] = 0.f;
        for (int d = 0; d < HD; d++) {
            float q[4], k[4];
            #pragma unroll
            for (int i = 0; i < 4; i++) { q[i] = Qs[ty * 4 + i][d]; k[i] = KVs[tx * 4 + i][d]; }
            #pragma unroll
            for (int i = 0; i < 4; i++)
                #pragma unroll
                for (int j = 0; j < 4; j++)
                    acc[i][j] = fmaf(q[i], k[j], acc[i][j]);
        }
        #pragma unroll
        for (int i = 0; i < 4; i++)
            #pragma unroll
            for (int j = 0; j < 4; j++) {
                const int t = ty * 4 + i, u = tx * 4 + j;
                Asc[t][u] = (u <= t) ? acc[i][j] : 0.f;
            }
    }
    __syncthreads();

    // Load V; compute denominators
    for (int i = tid; i < CHUNK * (HD / 8); i += 256) {
        const int t = i >> 3;
        const int d8 = (i & 7) * 8;
        put8(&KVs[t][d8], *(const uint4*)(g_vh + rowbase + (size_t)t * DD + d8));
    }
    if (tid < CHUNK) {
        float r = 0.f;
        for (int u = 0; u < CHUNK; u++) r += Asc[tid][u];
        float qz = 0.f;
        for (int d = 0; d < HD; d++) qz = fmaf(Qs[tid][d], zp[d], qz);
        den[tid] = r + qz + 1e-6f;
    }
    __syncthreads();

    // Phase 2: numerator = A @ V + Q @ S_prev ; divide; fp16 store
    {
        float o[4][4];
        #pragma unroll
        for (int i = 0; i < 4; i++)
            #pragma unroll
            for (int j = 0; j < 4; j++) o[i][j] = 0.f;
        for (int u = 0; u < CHUNK; u++) {
            float a[4], v[4];
            #pragma unroll
            for (int i = 0; i < 4; i++) { a[i] = Asc[ty * 4 + i][u]; v[i] = KVs[u][tx * 4 + i]; }
            #pragma unroll
            for (int i = 0; i < 4; i++)
                #pragma unroll
                for (int j = 0; j < 4; j++)
                    o[i][j] = fmaf(a[i], v[j], o[i][j]);
        }
        for (int d = 0; d < HD; d++) {
            float q[4], s[4];
            #pragma unroll
            for (int i = 0; i < 4; i++) { q[i] = Qs[ty * 4 + i][d]; s[i] = Ss[d][tx * 4 + i]; }
            #pragma unroll
            for (int i = 0; i < 4; i++)
                #pragma unroll
                for (int j = 0; j < 4; j++)
                    o[i][j] = fmaf(q[i], s[j], o[i][j]);
        }
        #pragma unroll
        for (int i = 0; i < 4; i++) {
            const float inv = 1.0f / den[ty * 4 + i];
            #pragma unroll
            for (int j = 0; j < 4; j += 2) {
                __half2 hv = __floats2half2_rn(o[i][j] * inv, o[i][j + 1] * inv);
                *(__half2*)(g_valh + rowbase + (size_t)(ty * 4 + i) * DD + tx * 4 + j) = hv;
            }
        }
    }
}

// ---------------------------------------------------------------------------
extern "C" void kernel_launch(void* const* d_in, const int* in_sizes, int n_in,
                              void* d_out, int out_size)
{
    (void)in_sizes; (void)n_in; (void)out_size;
    const float* x  = (const float*)d_in[0];
    const float* Wq = (const float*)d_in[2];
    const float* bq = (const float*)d_in[3];
    const float* Wk = (const float*)d_in[4];
    const float* bk = (const float*)d_in[5];
    const float* Wv = (const float*)d_in[6];
    const float* bv = (const float*)d_in[7];
    const float* Wo = (const float*)d_in[8];
    const float* bo = (const float*)d_in[9];
    float* out = (float*)d_out;

    __half *pxh, *pqh, *pkh, *pvh, *pvalh, *pwT;
    cudaGetSymbolAddress((void**)&pxh,   g_xh);
    cudaGetSymbolAddress((void**)&pqh,   g_qh);
    cudaGetSymbolAddress((void**)&pkh,   g_kh);
    cudaGetSymbolAddress((void**)&pvh,   g_vh);
    cudaGetSymbolAddress((void**)&pvalh, g_valh);
    cudaGetSymbolAddress((void**)&pwT,   g_wT);

    const int smbytes_g = 3 * 2 * 128 * 80;   // 61440 (3 stages x (A+B))
    cudaFuncSetAttribute(tc_gemm_k<0, 0>, cudaFuncAttributeMaxDynamicSharedMemorySize, smbytes_g);
    cudaFuncSetAttribute(tc_gemm_k<0, 1>, cudaFuncAttributeMaxDynamicSharedMemorySize, smbytes_g);
    cudaFuncSetAttribute(tc_gemm_k<1, 1>, cudaFuncAttributeMaxDynamicSharedMemorySize, smbytes_g);

    // convert inputs to fp16
    const int n4 = MTOT * DD / 4;
    convh_k<<<(n4 + 255) / 256, 256>>>((const float4*)x, (uint2*)pxh, n4);
    dim3 tgrid(DD / 32, DD / 32), tblk(32, 8);
    convT_k<<<tgrid, tblk>>>(Wq, pwT + 0 * (size_t)DD * DD);
    convT_k<<<tgrid, tblk>>>(Wk, pwT + 1 * (size_t)DD * DD);
    convT_k<<<tgrid, tblk>>>(Wv, pwT + 2 * (size_t)DD * DD);
    convT_k<<<tgrid, tblk>>>(Wo, pwT + 3 * (size_t)DD * DD);

    // projections (fp16 tensor cores, fp32 accumulate)
    dim3 ggrid(DD / 128, MTOT / 128);
    tc_gemm_k<1, 1><<<ggrid, 256, smbytes_g>>>(pxh, pwT + 0 * (size_t)DD * DD, bq, pqh);
    tc_gemm_k<1, 1><<<ggrid, 256, smbytes_g>>>(pxh, pwT + 1 * (size_t)DD * DD, bk, pkh);
    tc_gemm_k<0, 1><<<ggrid, 256, smbytes_g>>>(pxh, pwT + 2 * (size_t)DD * DD, bv, pvh);

    // linear attention (fp32 math, fp16 I/O)
    dim3 agrid(NCHUNK, NBH);
    kv_chunk_k<<<agrid, 256>>>();
    prefix_k<<<NBH, 1024>>>();
    const int smbytes_a = (3 * CHUNK * (HD + 1) + CHUNK * (CHUNK + 1) + 2 * CHUNK) * (int)sizeof(float);
    cudaFuncSetAttribute(attn_out_k, cudaFuncAttributeMaxDynamicSharedMemorySize, smbytes_a);
    attn_out_k<<<agrid, 256, smbytes_a>>>();

    // output projection -> fp32 out
    tc_gemm_k<0, 0><<<ggrid, 256, smbytes_g>>>(pvalh, pwT + 3 * (size_t)DD * DD, bo, out);
}

// round 5
// speedup vs baseline: 4.4437x; 1.3586x over previous
#include <cuda_runtime.h>
#include <cuda_fp16.h>
#include <cstdint>

// Problem constants (fixed by reference: B=4, S=2048, D=1024, H=16)
#define DD     1024
#define NH     16
#define HD     64
#define BATCH  4
#define SEQ    2048
#define MTOT   (BATCH * SEQ)      // 8192
#define CHUNK  64
#define NCHUNK (SEQ / CHUNK)      // 32
#define NBH    (BATCH * NH)       // 64
#define LDT    72                 // smem halves per tile row (64 + 8 pad)

// ---------------- scratch (allocation-free rule: __device__ globals) -------
__device__ float g_KV [NBH * NCHUNK * HD * HD];
__device__ float g_KS [NBH * NCHUNK * HD];

__device__ __half g_xh  [MTOT * DD];     // x in fp16
__device__ __half g_qh  [MTOT * DD];     // phi(xWq+b)
__device__ __half g_kh  [MTOT * DD];     // phi(xWk+b)
__device__ __half g_vh  [MTOT * DD];     // xWv+b
__device__ __half g_valh[MTOT * DD];     // attention output (fp16)
__device__ __half g_wT  [4][DD * DD];    // W^T fp16 (layout [N][K])

// ---------------------------------------------------------------------------
// PTX helpers (compute_100-safe: mma.sync / ldmatrix / cp.async only)
// ---------------------------------------------------------------------------
__device__ __forceinline__ uint32_t smem_u32(const void* p) {
    uint32_t a;
    asm("{ .reg .u64 t; cvta.to.shared.u64 t, %1; cvt.u32.u64 %0, t; }" : "=r"(a) : "l"(p));
    return a;
}

#define CP_ASYNC16(dst_u32, src_gptr) \
    asm volatile("cp.async.cg.shared.global [%0], [%1], 16;" \
                 :: "r"(dst_u32), "l"(src_gptr) : "memory")
#define CP_COMMIT() asm volatile("cp.async.commit_group;" ::: "memory")
#define CP_WAIT(n)  asm volatile("cp.async.wait_group %0;" :: "n"(n) : "memory")

#define LDSM_X4(r0, r1, r2, r3, addr) \
    asm volatile("ldmatrix.sync.aligned.m8n8.x4.shared.b16 {%0,%1,%2,%3}, [%4];" \
                 : "=r"(r0), "=r"(r1), "=r"(r2), "=r"(r3) : "r"(addr))

#define LDSM_X4_T(r0, r1, r2, r3, addr) \
    asm volatile("ldmatrix.sync.aligned.m8n8.x4.trans.shared.b16 {%0,%1,%2,%3}, [%4];" \
                 : "=r"(r0), "=r"(r1), "=r"(r2), "=r"(r3) : "r"(addr))

#define MMA16816F16(d, a, b0v, b1v) \
    asm volatile("mma.sync.aligned.m16n8k16.row.col.f32.f16.f16.f32 " \
                 "{%0,%1,%2,%3}, {%4,%5,%6,%7}, {%8,%9}, {%0,%1,%2,%3};" \
                 : "+f"((d)[0]), "+f"((d)[1]), "+f"((d)[2]), "+f"((d)[3]) \
                 : "r"((a)[0]), "r"((a)[1]), "r"((a)[2]), "r"((a)[3]), \
                   "r"(b0v), "r"(b1v))

__device__ __forceinline__ uint32_t packh2(float x, float y) {
    __half2 h = __floats2half2_rn(x, y);
    return *(uint32_t*)&h;
}

// ---------------------------------------------------------------------------
// fp32 -> fp16 (vectorized)
// ---------------------------------------------------------------------------
__global__ __launch_bounds__(256)
void convh_k(const float4* __restrict__ in, uint2* __restrict__ out, int n4)
{
    int i = blockIdx.x * 256 + threadIdx.x;
    if (i >= n4) return;
    float4 v = in[i];
    __half2 a = __floats2half2_rn(v.x, v.y);
    __half2 b = __floats2half2_rn(v.z, v.w);
    uint2 o;
    o.x = *(uint32_t*)&a;
    o.y = *(uint32_t*)&b;
    out[i] = o;
}

// Transpose + convert, all 4 weights in one launch (blockIdx.z selects W)
__global__ __launch_bounds__(256)
void convT_k(const float* __restrict__ W0, const float* __restrict__ W1,
             const float* __restrict__ W2, const float* __restrict__ W3,
             __half* __restrict__ hTbase)
{
    __shared__ float t[32][33];
    const float* W = (blockIdx.z == 0) ? W0 : (blockIdx.z == 1) ? W1
                   : (blockIdx.z == 2) ? W2 : W3;
    __half* hT = hTbase + (size_t)blockIdx.z * DD * DD;
    const int n0 = blockIdx.x * 32, k0 = blockIdx.y * 32;
    const int tx = threadIdx.x, ty = threadIdx.y;   // 32 x 8
    #pragma unroll
    for (int r = ty; r < 32; r += 8)
        t[r][tx] = W[(size_t)(k0 + r) * DD + n0 + tx];
    __syncthreads();
    #pragma unroll
    for (int r = ty; r < 32; r += 8)
        hT[(size_t)(n0 + r) * DD + k0 + tx] = __float2half_rn(t[tx][r]);
}

// ---------------------------------------------------------------------------
// fp16 tensor-core GEMM mainloop body (shared by fused-QKV and O kernels)
// CTA tile 128x128, BK=32, 8 warps (warp tile 64x32), 3-stage cp.async.
// ---------------------------------------------------------------------------
struct GemmCoords {
    int wm, wn, lane;
    uint32_t aOff, bOff;
    int c0row, c0k, c1row, c1k;
};

__device__ __forceinline__ GemmCoords gemm_coords(int tid) {
    GemmCoords g;
    const int wid = tid >> 5;
    g.lane = tid & 31;
    g.wm = wid & 1;
    g.wn = wid >> 1;
    g.aOff = (uint32_t)(g.wm * 64 + (g.lane & 15)) * 80 + (uint32_t)(g.lane >> 4) * 16;
    g.bOff = (uint32_t)(g.wn * 32 + (g.lane & 7) + ((g.lane >> 4) << 3)) * 80
           + (uint32_t)((g.lane >> 3) & 1) * 16;
    g.c0row = tid >> 2;         g.c0k = tid & 3;
    g.c1row = (tid + 256) >> 2; g.c1k = (tid + 256) & 3;
    return g;
}

template<int HALF_OUT>
__device__ __forceinline__
void gemm_body(const GemmCoords& g, uint32_t sb, uint64_t gA, uint64_t gB,
               int m0, int n0, bool act, const float* bias, void* Cg)
{
    constexpr int SROWB = 80, TILEB = 128 * SROWB, STAGEB = 2 * TILEB;
    constexpr int NIT = DD / 32;

    float acc[4][4][4];
    #pragma unroll
    for (int i = 0; i < 4; i++)
        #pragma unroll
        for (int j = 0; j < 4; j++)
            #pragma unroll
            for (int q = 0; q < 4; q++) acc[i][j][q] = 0.f;

    auto load_stage = [&](int slot, int kc) {
        const uint32_t sbase = sb + slot * STAGEB;
        {
            const uint32_t doff = g.c0row * SROWB + g.c0k * 16;
            const uint64_t oa = ((size_t)(m0 + g.c0row) * DD + kc + g.c0k * 8) * 2;
            const uint64_t ob = ((size_t)(n0 + g.c0row) * DD + kc + g.c0k * 8) * 2;
            CP_ASYNC16(sbase + doff, gA + oa);
            CP_ASYNC16(sbase + TILEB + doff, gB + ob);
        }
        {
            const uint32_t doff = g.c1row * SROWB + g.c1k * 16;
            const uint64_t oa = ((size_t)(m0 + g.c1row) * DD + kc + g.c1k * 8) * 2;
            const uint64_t ob = ((size_t)(n0 + g.c1row) * DD + kc + g.c1k * 8) * 2;
            CP_ASYNC16(sbase + doff, gA + oa);
            CP_ASYNC16(sbase + TILEB + doff, gB + ob);
        }
    };

    load_stage(0, 0);  CP_COMMIT();
    load_stage(1, 32); CP_COMMIT();
    load_stage(2, 64); CP_COMMIT();

    for (int it = 0; it < NIT; it++) {
        if (it < NIT - 2)       { CP_WAIT(2); }
        else if (it == NIT - 2) { CP_WAIT(1); }
        else                    { CP_WAIT(0); }
        __syncthreads();

        const int slot = it % 3;
        const uint32_t sA = sb + slot * STAGEB;
        const uint32_t sB = sA + TILEB;

        #pragma unroll
        for (int k16 = 0; k16 < 2; k16++) {
            const uint32_t kb = k16 * 32;
            uint32_t ah[4][4];
            #pragma unroll
            for (int mf = 0; mf < 4; mf++) {
                const uint32_t ao = g.aOff + mf * 16 * SROWB + kb;
                LDSM_X4(ah[mf][0], ah[mf][1], ah[mf][2], ah[mf][3], sA + ao);
            }
            uint32_t bb[2][4];
            #pragma unroll
            for (int gg = 0; gg < 2; gg++) {
                const uint32_t bo = g.bOff + gg * 16 * SROWB + kb;
                LDSM_X4(bb[gg][0], bb[gg][1], bb[gg][2], bb[gg][3], sB + bo);
            }
            #pragma unroll
            for (int mf = 0; mf < 4; mf++) {
                #pragma unroll
                for (int nf = 0; nf < 4; nf++) {
                    const int gg = nf >> 1, p = (nf & 1) * 2;
                    MMA16816F16(acc[mf][nf], ah[mf], bb[gg][p], bb[gg][p + 1]);
                }
            }
        }
        __syncthreads();
        if (it + 3 < NIT) { load_stage(slot, (it + 3) * 32); CP_COMMIT(); }
    }

    #pragma unroll
    for (int nf = 0; nf < 4; nf++) {
        const int cg = n0 + g.wn * 32 + nf * 8 + (g.lane & 3) * 2;
        const float b0 = __ldg(&bias[cg]);
        const float b1 = __ldg(&bias[cg + 1]);
        #pragma unroll
        for (int mf = 0; mf < 4; mf++) {
            const int rg = m0 + g.wm * 64 + mf * 16 + (g.lane >> 2);
            float v0 = acc[mf][nf][0] + b0;
            float v1 = acc[mf][nf][1] + b1;
            float v2 = acc[mf][nf][2] + b0;
            float v3 = acc[mf][nf][3] + b1;
            if (act) {
                v0 = (v0 > 0.f) ? (v0 + 1.f) : __expf(v0);
                v1 = (v1 > 0.f) ? (v1 + 1.f) : __expf(v1);
                v2 = (v2 > 0.f) ? (v2 + 1.f) : __expf(v2);
                v3 = (v3 > 0.f) ? (v3 + 1.f) : __expf(v3);
            }
            if (HALF_OUT) {
                __half* Ch = (__half*)Cg;
                *(__half2*)(Ch + (size_t)rg * DD + cg)       = __floats2half2_rn(v0, v1);
                *(__half2*)(Ch + (size_t)(rg + 8) * DD + cg) = __floats2half2_rn(v2, v3);
            } else {
                float* Cf = (float*)Cg;
                *(float2*)(Cf + (size_t)rg * DD + cg)       = make_float2(v0, v1);
                *(float2*)(Cf + (size_t)(rg + 8) * DD + cg) = make_float2(v2, v3);
            }
        }
    }
}

// Fused Q/K/V projections: grid.x = 3*8 (which*8 + nblk), grid.y = M/128
__global__ __launch_bounds__(256, 1)
void qkv_gemm_k(const __half* __restrict__ A, const __half* __restrict__ wT,
                const float* __restrict__ bq, const float* __restrict__ bk,
                const float* __restrict__ bv)
{
    extern __shared__ char smem[];
    const int which = blockIdx.x >> 3;
    const int n0 = (blockIdx.x & 7) * 128;
    const int m0 = blockIdx.y * 128;
    const __half* BT = wT + (size_t)which * DD * DD;
    const float* bias = (which == 0) ? bq : (which == 1) ? bk : bv;
    __half* out = (which == 0) ? g_qh : (which == 1) ? g_kh : g_vh;
    GemmCoords g = gemm_coords(threadIdx.x);
    gemm_body<1>(g, smem_u32(smem), __cvta_generic_to_global(A),
                 __cvta_generic_to_global(BT), m0, n0, which < 2, bias, out);
}

// Output projection: fp16 A, fp32 C
__global__ __launch_bounds__(256, 1)
void out_gemm_k(const __half* __restrict__ A, const __half* __restrict__ BT,
                const float* __restrict__ bias, float* __restrict__ Cg)
{
    extern __shared__ char smem[];
    GemmCoords g = gemm_coords(threadIdx.x);
    gemm_body<0>(g, smem_u32(smem), __cvta_generic_to_global(A),
                 __cvta_generic_to_global(BT), blockIdx.y * 128, blockIdx.x * 128,
                 false, bias, Cg);
}

// ---------------------------------------------------------------------------
// Tile loader: 64x64 fp16 gmem rows -> smem [64][LDT]
// ---------------------------------------------------------------------------
__device__ __forceinline__
void load_tile_h(__half (*dst)[LDT], const __half* src, size_t rowbase, int tid)
{
    #pragma unroll
    for (int j = 0; j < 4; j++) {
        const int idx = tid + 128 * j;       // 0..511
        const int row = idx >> 3;
        const int c = (idx & 7) * 8;
        *(uint4*)&dst[row][c] = *(const uint4*)(src + rowbase + (size_t)row * DD + c);
    }
}

// ---------------------------------------------------------------------------
// Pass A (tensor core): KV_c[d][m] = sum_t K[t][d] V[t][m]; ks_c[d] = sum_t K[t][d]
// 128 threads; warp w -> d rows [16w, 16w+16)
// ---------------------------------------------------------------------------
__global__ __launch_bounds__(128)
void kv_chunk_tc()
{
    __shared__ __half Ks[CHUNK][LDT];
    __shared__ __half Vs[CHUNK][LDT];

    const int c = blockIdx.x, bh = blockIdx.y;
    const int b = bh >> 4, h = bh & 15;
    const int tid = threadIdx.x;
    const int w = tid >> 5, l = tid & 31;
    const size_t rowbase = (size_t)(b * SEQ + c * CHUNK) * DD + h * HD;

    load_tile_h(Ks, g_kh, rowbase, tid);
    load_tile_h(Vs, g_vh, rowbase, tid);
    __syncthreads();

    // trans-ldmatrix lane coords (source rows = contraction index)
    const int tRow = ((l >> 4) << 3) + (l & 7);    // k-row within k16 (A-trans)
    const int tColA = ((l >> 3) & 1) * 8;          // m-octet within m16 (A-trans)
    const int tRowB = ((l >> 3) & 1) * 8 + (l & 7);// k-row within k16 (B-trans)
    const int tColB = (l >> 4) * 8;                // n-octet within n16 (B-trans)

    float acc[8][4];
    #pragma unroll
    for (int i = 0; i < 8; i++)
        #pragma unroll
        for (int q = 0; q < 4; q++) acc[i][q] = 0.f;

    #pragma unroll
    for (int kk = 0; kk < 4; kk++) {               // t in [16kk, 16kk+16)
        uint32_t a[4];
        LDSM_X4_T(a[0], a[1], a[2], a[3],
                  smem_u32(&Ks[kk * 16 + tRow][w * 16 + tColA]));
        #pragma unroll
        for (int gN = 0; gN < 4; gN++) {           // m-octet pair base gN*16
            uint32_t r0, r1, r2, r3;
            LDSM_X4_T(r0, r1, r2, r3,
                      smem_u32(&Vs[kk * 16 + tRowB][gN * 16 + tColB]));
            MMA16816F16(acc[2 * gN],     a, r0, r1);
            MMA16816F16(acc[2 * gN + 1], a, r2, r3);
        }
    }

    float* outp = g_KV + (size_t)(bh * NCHUNK + c) * HD * HD;
    const int r0 = w * 16 + (l >> 2);
    #pragma unroll
    for (int nf = 0; nf < 8; nf++) {
        const int col = nf * 8 + 2 * (l & 3);
        *(float2*)(outp + (size_t)r0 * HD + col)       = make_float2(acc[nf][0], acc[nf][1]);
        *(float2*)(outp + (size_t)(r0 + 8) * HD + col) = make_float2(acc[nf][2], acc[nf][3]);
    }

    if (tid < HD) {
        float s = 0.f;
        #pragma unroll 8
        for (int t = 0; t < CHUNK; t++) s += __half2float(Ks[t][tid]);
        g_KS[(bh * NCHUNK + c) * HD + tid] = s;
    }
}

// ---------------------------------------------------------------------------
// Pass B: in-place EXCLUSIVE prefix over chunks (per bh)
// ---------------------------------------------------------------------------
__global__ __launch_bounds__(1024)
void prefix_k()
{
    const int bh = blockIdx.x;
    const int tid = threadIdx.x;
    float4 run = make_float4(0.f, 0.f, 0.f, 0.f);
    float* base = g_KV + (size_t)bh * NCHUNK * HD * HD;
    for (int c = 0; c < NCHUNK; c++) {
        float4* p = (float4*)(base + (size_t)c * HD * HD) + tid;
        float4 v = *p;
        *p = run;
        run.x += v.x; run.y += v.y; run.z += v.z; run.w += v.w;
    }
    if (tid < HD) {
        float r = 0.f;
        float* zb = g_KS + (size_t)bh * NCHUNK * HD + tid;
        for (int c = 0; c < NCHUNK; c++) { float v = zb[(size_t)c * HD]; zb[(size_t)c * HD] = r; r += v; }
    }
}

// ---------------------------------------------------------------------------
// Pass C (tensor core): out = (tril(QK^T) V + Q S_prev) / (rowsum + Q.z + eps)
// 128 threads; warp w -> t rows [16w, 16w+16)
// ---------------------------------------------------------------------------
__global__ __launch_bounds__(128)
void attn_out_tc()
{
    __shared__ __half Qs [CHUNK][LDT];
    __shared__ __half Ks [CHUNK][LDT];
    __shared__ __half Vs [CHUNK][LDT];
    __shared__ __half Sph[HD][LDT];
    __shared__ float rs[CHUNK], den[CHUNK], zp[HD];

    const int c = blockIdx.x, bh = blockIdx.y;
    const int b = bh >> 4, h = bh & 15;
    const int tid = threadIdx.x;
    const int w = tid >> 5, l = tid & 31;
    const size_t rowbase = (size_t)(b * SEQ + c * CHUNK) * DD + h * HD;
    const float* Sp = g_KV + (size_t)(bh * NCHUNK + c) * HD * HD;

    load_tile_h(Qs, g_qh, rowbase, tid);
    load_tile_h(Ks, g_kh, rowbase, tid);
    load_tile_h(Vs, g_vh, rowbase, tid);
    #pragma unroll
    for (int j = 0; j < 8; j++) {                  // Sp fp32 -> fp16 smem
        const int idx = tid + 128 * j;             // 0..1023
        const int row = idx >> 4;
        const int c4 = (idx & 15) * 4;
        float4 v = *(const float4*)(Sp + (size_t)row * HD + c4);
        uint2 o;
        o.x = packh2(v.x, v.y);
        o.y = packh2(v.z, v.w);
        *(uint2*)&Sph[row][c4] = o;
    }
    if (tid < HD) zp[tid] = g_KS[(bh * NCHUNK + c) * HD + tid];
    __syncthreads();

    // non-trans lane coords (as in the validated GEMM kernel)
    const uint32_t aRow = w * 16 + (l & 15);       // Q rows
    const uint32_t aK = (l >> 4) * 8;              // k-octet (halves)
    const uint32_t bRow = (l & 7) + ((l >> 4) << 3);
    const uint32_t bK = ((l >> 3) & 1) * 8;
    // trans lane coords
    const int tRowB = ((l >> 3) & 1) * 8 + (l & 7);
    const int tColB = (l >> 4) * 8;

    // ---- Phase 1: S = Q K^T (contract d) ----
    float accS[8][4];
    #pragma unroll
    for (int i = 0; i < 8; i++)
        #pragma unroll
        for (int q = 0; q < 4; q++) accS[i][q] = 0.f;

    #pragma unroll
    for (int kk = 0; kk < 4; kk++) {
        uint32_t a[4];
        LDSM_X4(a[0], a[1], a[2], a[3], smem_u32(&Qs[aRow][kk * 16 + aK]));
        #pragma unroll
        for (int gN = 0; gN < 4; gN++) {
            uint32_t r0, r1, r2, r3;
            LDSM_X4(r0, r1, r2, r3, smem_u32(&Ks[gN * 16 + bRow][kk * 16 + bK]));
            MMA16816F16(accS[2 * gN],     a, r0, r1);
            MMA16816F16(accS[2 * gN + 1], a, r2, r3);
        }
    }

    // ---- mask tril + row sums (fp32, pre-rounding) ----
    const int row0 = w * 16 + (l >> 2);
    const int row1 = row0 + 8;
    float sum0 = 0.f, sum1 = 0.f;
    #pragma unroll
    for (int nf = 0; nf < 8; nf++) {
        #pragma unroll
        for (int jj = 0; jj < 2; jj++) {
            const int col = nf * 8 + 2 * (l & 3) + jj;
            accS[nf][jj]     = (col <= row0) ? accS[nf][jj]     : 0.f;
            accS[nf][2 + jj] = (col <= row1) ? accS[nf][2 + jj] : 0.f;
            sum0 += accS[nf][jj];
            sum1 += accS[nf][2 + jj];
        }
    }
    sum0 += __shfl_xor_sync(0xFFFFFFFF, sum0, 1);
    sum0 += __shfl_xor_sync(0xFFFFFFFF, sum0, 2);
    sum1 += __shfl_xor_sync(0xFFFFFFFF, sum1, 1);
    sum1 += __shfl_xor_sync(0xFFFFFFFF, sum1, 2);
    if ((l & 3) == 0) { rs[row0] = sum0; rs[row1] = sum1; }
    __syncthreads();
    if (tid < CHUNK) {
        float qz = 0.f;
        #pragma unroll 8
        for (int d = 0; d < HD; d++) qz = fmaf(__half2float(Qs[tid][d]), zp[d], qz);
        den[tid] = rs[tid] + qz + 1e-6f;
    }
    __syncthreads();

    // ---- Phase 2: O = S V + Q S_prev ----
    float accO[8][4];
    #pragma unroll
    for (int i = 0; i < 8; i++)
        #pragma unroll
        for (int q = 0; q < 4; q++) accO[i][q] = 0.f;

    // S V (contract u); A fragments built from accS (fp16 rounding of scores)
    #pragma unroll
    for (int kk = 0; kk < 4; kk++) {
        uint32_t a[4];
        a[0] = packh2(accS[2 * kk][0],     accS[2 * kk][1]);
        a[1] = packh2(accS[2 * kk][2],     accS[2 * kk][3]);
        a[2] = packh2(accS[2 * kk + 1][0], accS[2 * kk + 1][1]);
        a[3] = packh2(accS[2 * kk + 1][2], accS[2 * kk + 1][3]);
        #pragma unroll
        for (int gN = 0; gN < 4; gN++) {
            uint32_t r0, r1, r2, r3;
            LDSM_X4_T(r0, r1, r2, r3,
                      smem_u32(&Vs[kk * 16 + tRowB][gN * 16 + tColB]));
            MMA16816F16(accO[2 * gN],     a, r0, r1);
            MMA16816F16(accO[2 * gN + 1], a, r2, r3);
        }
    }
    // Q S_prev (contract d); B = Sph[d][m] trans
    #pragma unroll
    for (int kk = 0; kk < 4; kk++) {
        uint32_t a[4];
        LDSM_X4(a[0], a[1], a[2], a[3], smem_u32(&Qs[aRow][kk * 16 + aK]));
        #pragma unroll
        for (int gN = 0; gN < 4; gN++) {
            uint32_t r0, r1, r2, r3;
            LDSM_X4_T(r0, r1, r2, r3,
                      smem_u32(&Sph[kk * 16 + tRowB][gN * 16 + tColB]));
            MMA16816F16(accO[2 * gN],     a, r0, r1);
            MMA16816F16(accO[2 * gN + 1], a, r2, r3);
        }
    }

    // ---- divide + fp16 store ----
    const float inv0 = 1.0f / den[row0];
    const float inv1 = 1.0f / den[row1];
    #pragma unroll
    for (int nf = 0; nf < 8; nf++) {
        const int col = nf * 8 + 2 * (l & 3);
        *(uint32_t*)(g_valh + rowbase + (size_t)row0 * DD + col) =
            packh2(accO[nf][0] * inv0, accO[nf][1] * inv0);
        *(uint32_t*)(g_valh + rowbase + (size_t)row1 * DD + col) =
            packh2(accO[nf][2] * inv1, accO[nf][3] * inv1);
    }
}

// ---------------------------------------------------------------------------
extern "C" void kernel_launch(void* const* d_in, const int* in_sizes, int n_in,
                              void* d_out, int out_size)
{
    (void)in_sizes; (void)n_in; (void)out_size;
    const float* x  = (const float*)d_in[0];
    const float* Wq = (const float*)d_in[2];
    const float* bq = (const float*)d_in[3];
    const float* Wk = (const float*)d_in[4];
    const float* bk = (const float*)d_in[5];
    const float* Wv = (const float*)d_in[6];
    const float* bv = (const float*)d_in[7];
    const float* Wo = (const float*)d_in[8];
    const float* bo = (const float*)d_in[9];
    float* out = (float*)d_out;

    __half *pxh, *pvalh, *pwT;
    cudaGetSymbolAddress((void**)&pxh,   g_xh);
    cudaGetSymbolAddress((void**)&pvalh, g_valh);
    cudaGetSymbolAddress((void**)&pwT,   g_wT);

    const int smbytes_g = 3 * 2 * 128 * 80;   // 61440
    cudaFuncSetAttribute(qkv_gemm_k, cudaFuncAttributeMaxDynamicSharedMemorySize, smbytes_g);
    cudaFuncSetAttribute(out_gemm_k, cudaFuncAttributeMaxDynamicSharedMemorySize, smbytes_g);

    // convert inputs to fp16
    const int n4 = MTOT * DD / 4;
    convh_k<<<(n4 + 255) / 256, 256>>>((const float4*)x, (uint2*)pxh, n4);
    dim3 tgrid(DD / 32, DD / 32, 4), tblk(32, 8);
    convT_k<<<tgrid, tblk>>>(Wq, Wk, Wv, Wo, pwT);

    // fused Q/K/V projections (one launch, 1536 CTAs)
    qkv_gemm_k<<<dim3(3 * DD / 128, MTOT / 128), 256, smbytes_g>>>(pxh, pwT, bq, bk, bv);

    // linear attention (tensor-core passes)
    dim3 agrid(NCHUNK, NBH);
    kv_chunk_tc<<<agrid, 128>>>();
    prefix_k<<<NBH, 1024>>>();
    attn_out_tc<<<agrid, 128>>>();

    // output projection -> fp32 out
    out_gemm_k<<<dim3(DD / 128, MTOT / 128), 256, smbytes_g>>>(
        pvalh, pwT + 3 * (size_t)DD * DD, bo, out);
}

// round 6
// speedup vs baseline: 5.6586x; 1.2734x over previous
#include <cuda_runtime.h>
#include <cuda_fp16.h>
#include <cstdint>

// Problem constants (fixed by reference: B=4, S=2048, D=1024, H=16)
#define DD     1024
#define NH     16
#define HD     64
#define BATCH  4
#define SEQ    2048
#define MTOT   (BATCH * SEQ)      // 8192
#define CHUNK  64
#define NCHUNK (SEQ / CHUNK)      // 32
#define NBH    (BATCH * NH)       // 64
#define LDT    72                 // smem halves per tile row (64 + 8 pad)

// ---------------- scratch (allocation-free rule: __device__ globals) -------
__device__ float g_KV [NBH * NCHUNK * HD * HD];
__device__ float g_KS [NBH * NCHUNK * HD];

__device__ __half g_xh  [MTOT * DD];     // x in fp16
__device__ __half g_qh  [MTOT * DD];     // phi(xWq+b)
__device__ __half g_kh  [MTOT * DD];     // phi(xWk+b)
__device__ __half g_vh  [MTOT * DD];     // xWv+b
__device__ __half g_valh[MTOT * DD];     // attention output (fp16)
__device__ __half g_wT  [4][DD * DD];    // W^T fp16 (layout [N][K])

// ---------------------------------------------------------------------------
// PTX helpers (compute_100-safe: mma.sync / ldmatrix / cp.async only)
// ---------------------------------------------------------------------------
__device__ __forceinline__ uint32_t smem_u32(const void* p) {
    uint32_t a;
    asm("{ .reg .u64 t; cvta.to.shared.u64 t, %1; cvt.u32.u64 %0, t; }" : "=r"(a) : "l"(p));
    return a;
}

#define CP_ASYNC16(dst_u32, src_gptr) \
    asm volatile("cp.async.cg.shared.global [%0], [%1], 16;" \
                 :: "r"(dst_u32), "l"(src_gptr) : "memory")
#define CP_COMMIT() asm volatile("cp.async.commit_group;" ::: "memory")
#define CP_WAIT(n)  asm volatile("cp.async.wait_group %0;" :: "n"(n) : "memory")

#define LDSM_X4(r0, r1, r2, r3, addr) \
    asm volatile("ldmatrix.sync.aligned.m8n8.x4.shared.b16 {%0,%1,%2,%3}, [%4];" \
                 : "=r"(r0), "=r"(r1), "=r"(r2), "=r"(r3) : "r"(addr))

#define LDSM_X4_T(r0, r1, r2, r3, addr) \
    asm volatile("ldmatrix.sync.aligned.m8n8.x4.trans.shared.b16 {%0,%1,%2,%3}, [%4];" \
                 : "=r"(r0), "=r"(r1), "=r"(r2), "=r"(r3) : "r"(addr))

#define MMA16816F16(d, a, b0v, b1v) \
    asm volatile("mma.sync.aligned.m16n8k16.row.col.f32.f16.f16.f32 " \
                 "{%0,%1,%2,%3}, {%4,%5,%6,%7}, {%8,%9}, {%0,%1,%2,%3};" \
                 : "+f"((d)[0]), "+f"((d)[1]), "+f"((d)[2]), "+f"((d)[3]) \
                 : "r"((a)[0]), "r"((a)[1]), "r"((a)[2]), "r"((a)[3]), \
                   "r"(b0v), "r"(b1v))

__device__ __forceinline__ uint32_t packh2(float x, float y) {
    __half2 h = __floats2half2_rn(x, y);
    return *(uint32_t*)&h;
}

// ---------------------------------------------------------------------------
// fp32 -> fp16, 8 elements/thread, grid-stride
// ---------------------------------------------------------------------------
__global__ __launch_bounds__(256)
void convh_k(const float4* __restrict__ in, uint4* __restrict__ out, int n8)
{
    for (int i = blockIdx.x * 256 + threadIdx.x; i < n8; i += gridDim.x * 256) {
        float4 a = in[2 * i];
        float4 b = in[2 * i + 1];
        uint4 o;
        o.x = packh2(a.x, a.y);
        o.y = packh2(a.z, a.w);
        o.z = packh2(b.x, b.y);
        o.w = packh2(b.z, b.w);
        out[i] = o;
    }
}

// Transpose + convert, all 4 weights in one launch (blockIdx.z selects W)
__global__ __launch_bounds__(256)
void convT_k(const float* __restrict__ W0, const float* __restrict__ W1,
             const float* __restrict__ W2, const float* __restrict__ W3,
             __half* __restrict__ hTbase)
{
    __shared__ float t[32][33];
    const float* W = (blockIdx.z == 0) ? W0 : (blockIdx.z == 1) ? W1
                   : (blockIdx.z == 2) ? W2 : W3;
    __half* hT = hTbase + (size_t)blockIdx.z * DD * DD;
    const int n0 = blockIdx.x * 32, k0 = blockIdx.y * 32;
    const int tx = threadIdx.x, ty = threadIdx.y;   // 32 x 8
    #pragma unroll
    for (int r = ty; r < 32; r += 8)
        t[r][tx] = W[(size_t)(k0 + r) * DD + n0 + tx];
    __syncthreads();
    #pragma unroll
    for (int r = ty; r < 32; r += 8)
        hT[(size_t)(n0 + r) * DD + k0 + tx] = __float2half_rn(t[tx][r]);
}

// ---------------------------------------------------------------------------
// fp16 tensor-core GEMM mainloop body
// CTA tile 128x128, BK=32, 8 warps (warp tile 64x32), 3-stage cp.async,
// single __syncthreads per k-iteration, 2 CTAs/SM.
// ---------------------------------------------------------------------------
struct GemmCoords {
    int wm, wn, lane;
    uint32_t aOff, bOff;
    int c0row, c0k, c1row, c1k;
};

__device__ __forceinline__ GemmCoords gemm_coords(int tid) {
    GemmCoords g;
    const int wid = tid >> 5;
    g.lane = tid & 31;
    g.wm = wid & 1;
    g.wn = wid >> 1;
    g.aOff = (uint32_t)(g.wm * 64 + (g.lane & 15)) * 80 + (uint32_t)(g.lane >> 4) * 16;
    g.bOff = (uint32_t)(g.wn * 32 + (g.lane & 7) + ((g.lane >> 4) << 3)) * 80
           + (uint32_t)((g.lane >> 3) & 1) * 16;
    g.c0row = tid >> 2;         g.c0k = tid & 3;
    g.c1row = (tid + 256) >> 2; g.c1k = (tid + 256) & 3;
    return g;
}

template<int HALF_OUT>
__device__ __forceinline__
void gemm_body(const GemmCoords& g, uint32_t sb, uint64_t gA, uint64_t gB,
               int m0, int n0, bool act, const float* bias, void* Cg)
{
    constexpr int SROWB = 80, TILEB = 128 * SROWB, STAGEB = 2 * TILEB;
    constexpr int NIT = DD / 32;

    float acc[4][4][4];
    #pragma unroll
    for (int i = 0; i < 4; i++)
        #pragma unroll
        for (int j = 0; j < 4; j++)
            #pragma unroll
            for (int q = 0; q < 4; q++) acc[i][j][q] = 0.f;

    auto load_stage = [&](int slot, int kc) {
        const uint32_t sbase = sb + slot * STAGEB;
        {
            const uint32_t doff = g.c0row * SROWB + g.c0k * 16;
            const uint64_t oa = ((size_t)(m0 + g.c0row) * DD + kc + g.c0k * 8) * 2;
            const uint64_t ob = ((size_t)(n0 + g.c0row) * DD + kc + g.c0k * 8) * 2;
            CP_ASYNC16(sbase + doff, gA + oa);
            CP_ASYNC16(sbase + TILEB + doff, gB + ob);
        }
        {
            const uint32_t doff = g.c1row * SROWB + g.c1k * 16;
            const uint64_t oa = ((size_t)(m0 + g.c1row) * DD + kc + g.c1k * 8) * 2;
            const uint64_t ob = ((size_t)(n0 + g.c1row) * DD + kc + g.c1k * 8) * 2;
            CP_ASYNC16(sbase + doff, gA + oa);
            CP_ASYNC16(sbase + TILEB + doff, gB + ob);
        }
    };

    load_stage(0, 0);  CP_COMMIT();
    load_stage(1, 32); CP_COMMIT();

    for (int it = 0; it < NIT; it++) {
        if (it + 1 < NIT) { CP_WAIT(1); } else { CP_WAIT(0); }
        __syncthreads();
        // target slot (it+2)%3 == (it-1)%3: all warps finished reading it at
        // the barrier above, so one sync per iteration suffices.
        if (it + 2 < NIT) { load_stage((it + 2) % 3, (it + 2) * 32); CP_COMMIT(); }

        const int slot = it % 3;
        const uint32_t sA = sb + slot * STAGEB;
        const uint32_t sB = sA + TILEB;

        #pragma unroll
        for (int k16 = 0; k16 < 2; k16++) {
            const uint32_t kb = k16 * 32;
            uint32_t ah[4][4];
            #pragma unroll
            for (int mf = 0; mf < 4; mf++) {
                const uint32_t ao = g.aOff + mf * 16 * SROWB + kb;
                LDSM_X4(ah[mf][0], ah[mf][1], ah[mf][2], ah[mf][3], sA + ao);
            }
            uint32_t bb[2][4];
            #pragma unroll
            for (int gg = 0; gg < 2; gg++) {
                const uint32_t bo = g.bOff + gg * 16 * SROWB + kb;
                LDSM_X4(bb[gg][0], bb[gg][1], bb[gg][2], bb[gg][3], sB + bo);
            }
            #pragma unroll
            for (int mf = 0; mf < 4; mf++) {
                #pragma unroll
                for (int nf = 0; nf < 4; nf++) {
                    const int gg = nf >> 1, p = (nf & 1) * 2;
                    MMA16816F16(acc[mf][nf], ah[mf], bb[gg][p], bb[gg][p + 1]);
                }
            }
        }
    }

    #pragma unroll
    for (int nf = 0; nf < 4; nf++) {
        const int cg = n0 + g.wn * 32 + nf * 8 + (g.lane & 3) * 2;
        const float b0 = __ldg(&bias[cg]);
        const float b1 = __ldg(&bias[cg + 1]);
        #pragma unroll
        for (int mf = 0; mf < 4; mf++) {
            const int rg = m0 + g.wm * 64 + mf * 16 + (g.lane >> 2);
            float v0 = acc[mf][nf][0] + b0;
            float v1 = acc[mf][nf][1] + b1;
            float v2 = acc[mf][nf][2] + b0;
            float v3 = acc[mf][nf][3] + b1;
            if (act) {
                v0 = (v0 > 0.f) ? (v0 + 1.f) : __expf(v0);
                v1 = (v1 > 0.f) ? (v1 + 1.f) : __expf(v1);
                v2 = (v2 > 0.f) ? (v2 + 1.f) : __expf(v2);
                v3 = (v3 > 0.f) ? (v3 + 1.f) : __expf(v3);
            }
            if (HALF_OUT) {
                __half* Ch = (__half*)Cg;
                *(__half2*)(Ch + (size_t)rg * DD + cg)       = __floats2half2_rn(v0, v1);
                *(__half2*)(Ch + (size_t)(rg + 8) * DD + cg) = __floats2half2_rn(v2, v3);
            } else {
                float* Cf = (float*)Cg;
                *(float2*)(Cf + (size_t)rg * DD + cg)       = make_float2(v0, v1);
                *(float2*)(Cf + (size_t)(rg + 8) * DD + cg) = make_float2(v2, v3);
            }
        }
    }
}

// Fused Q/K/V projections: grid.x = 3*8 (which*8 + nblk), grid.y = M/128
__global__ __launch_bounds__(256, 2)
void qkv_gemm_k(const __half* __restrict__ A, const __half* __restrict__ wT,
                const float* __restrict__ bq, const float* __restrict__ bk,
                const float* __restrict__ bv)
{
    extern __shared__ char smem[];
    const int which = blockIdx.x >> 3;
    const int n0 = (blockIdx.x & 7) * 128;
    const int m0 = blockIdx.y * 128;
    const __half* BT = wT + (size_t)which * DD * DD;
    const float* bias = (which == 0) ? bq : (which == 1) ? bk : bv;
    __half* out = (which == 0) ? g_qh : (which == 1) ? g_kh : g_vh;
    GemmCoords g = gemm_coords(threadIdx.x);
    gemm_body<1>(g, smem_u32(smem), __cvta_generic_to_global(A),
                 __cvta_generic_to_global(BT), m0, n0, which < 2, bias, out);
}

// Output projection: fp16 A, fp32 C
__global__ __launch_bounds__(256, 2)
void out_gemm_k(const __half* __restrict__ A, const __half* __restrict__ BT,
                const float* __restrict__ bias, float* __restrict__ Cg)
{
    extern __shared__ char smem[];
    GemmCoords g = gemm_coords(threadIdx.x);
    gemm_body<0>(g, smem_u32(smem), __cvta_generic_to_global(A),
                 __cvta_generic_to_global(BT), blockIdx.y * 128, blockIdx.x * 128,
                 false, bias, Cg);
}

// ---------------------------------------------------------------------------
// Tile loader: 64x64 fp16 gmem rows -> smem [64][LDT]
// ---------------------------------------------------------------------------
__device__ __forceinline__
void load_tile_h(__half (*dst)[LDT], const __half* src, size_t rowbase, int tid)
{
    #pragma unroll
    for (int j = 0; j < 4; j++) {
        const int idx = tid + 128 * j;       // 0..511
        const int row = idx >> 3;
        const int c = (idx & 7) * 8;
        *(uint4*)&dst[row][c] = *(const uint4*)(src + rowbase + (size_t)row * DD + c);
    }
}

// ---------------------------------------------------------------------------
// Pass A (tensor core): KV_c[d][m] = sum_t K[t][d] V[t][m]; ks_c[d] = sum_t K[t][d]
// ---------------------------------------------------------------------------
__global__ __launch_bounds__(128)
void kv_chunk_tc()
{
    __shared__ __half Ks[CHUNK][LDT];
    __shared__ __half Vs[CHUNK][LDT];

    const int c = blockIdx.x, bh = blockIdx.y;
    const int b = bh >> 4, h = bh & 15;
    const int tid = threadIdx.x;
    const int w = tid >> 5, l = tid & 31;
    const size_t rowbase = (size_t)(b * SEQ + c * CHUNK) * DD + h * HD;

    load_tile_h(Ks, g_kh, rowbase, tid);
    load_tile_h(Vs, g_vh, rowbase, tid);
    __syncthreads();

    const int tRow = ((l >> 4) << 3) + (l & 7);
    const int tColA = ((l >> 3) & 1) * 8;
    const int tRowB = ((l >> 3) & 1) * 8 + (l & 7);
    const int tColB = (l >> 4) * 8;

    float acc[8][4];
    #pragma unroll
    for (int i = 0; i < 8; i++)
        #pragma unroll
        for (int q = 0; q < 4; q++) acc[i][q] = 0.f;

    #pragma unroll
    for (int kk = 0; kk < 4; kk++) {
        uint32_t a[4];
        LDSM_X4_T(a[0], a[1], a[2], a[3],
                  smem_u32(&Ks[kk * 16 + tRow][w * 16 + tColA]));
        #pragma unroll
        for (int gN = 0; gN < 4; gN++) {
            uint32_t r0, r1, r2, r3;
            LDSM_X4_T(r0, r1, r2, r3,
                      smem_u32(&Vs[kk * 16 + tRowB][gN * 16 + tColB]));
            MMA16816F16(acc[2 * gN],     a, r0, r1);
            MMA16816F16(acc[2 * gN + 1], a, r2, r3);
        }
    }

    float* outp = g_KV + (size_t)(bh * NCHUNK + c) * HD * HD;
    const int r0 = w * 16 + (l >> 2);
    #pragma unroll
    for (int nf = 0; nf < 8; nf++) {
        const int col = nf * 8 + 2 * (l & 3);
        *(float2*)(outp + (size_t)r0 * HD + col)       = make_float2(acc[nf][0], acc[nf][1]);
        *(float2*)(outp + (size_t)(r0 + 8) * HD + col) = make_float2(acc[nf][2], acc[nf][3]);
    }

    if (tid < HD) {
        float s = 0.f;
        #pragma unroll 8
        for (int t = 0; t < CHUNK; t++) s += __half2float(Ks[t][tid]);
        g_KS[(bh * NCHUNK + c) * HD + tid] = s;
    }
}

// ---------------------------------------------------------------------------
// Pass B: in-place EXCLUSIVE prefix over chunks (per bh)
// ---------------------------------------------------------------------------
__global__ __launch_bounds__(1024)
void prefix_k()
{
    const int bh = blockIdx.x;
    const int tid = threadIdx.x;
    float4 run = make_float4(0.f, 0.f, 0.f, 0.f);
    float* base = g_KV + (size_t)bh * NCHUNK * HD * HD;
    for (int c = 0; c < NCHUNK; c++) {
        float4* p = (float4*)(base + (size_t)c * HD * HD) + tid;
        float4 v = *p;
        *p = run;
        run.x += v.x; run.y += v.y; run.z += v.z; run.w += v.w;
    }
    if (tid < HD) {
        float r = 0.f;
        float* zb = g_KS + (size_t)bh * NCHUNK * HD + tid;
        for (int c = 0; c < NCHUNK; c++) { float v = zb[(size_t)c * HD]; zb[(size_t)c * HD] = r; r += v; }
    }
}

// ---------------------------------------------------------------------------
// Pass C (tensor core): out = (tril(QK^T) V + Q S_prev) / (rowsum + Q.z + eps)
// ---------------------------------------------------------------------------
__global__ __launch_bounds__(128)
void attn_out_tc()
{
    __shared__ __half Qs [CHUNK][LDT];
    __shared__ __half Ks [CHUNK][LDT];
    __shared__ __half Vs [CHUNK][LDT];
    __shared__ __half Sph[HD][LDT];
    __shared__ float rs[CHUNK], den[CHUNK], zp[HD];

    const int c = blockIdx.x, bh = blockIdx.y;
    const int b = bh >> 4, h = bh & 15;
    const int tid = threadIdx.x;
    const int w = tid >> 5, l = tid & 31;
    const size_t rowbase = (size_t)(b * SEQ + c * CHUNK) * DD + h * HD;
    const float* Sp = g_KV + (size_t)(bh * NCHUNK + c) * HD * HD;

    load_tile_h(Qs, g_qh, rowbase, tid);
    load_tile_h(Ks, g_kh, rowbase, tid);
    load_tile_h(Vs, g_vh, rowbase, tid);
    #pragma unroll
    for (int j = 0; j < 8; j++) {
        const int idx = tid + 128 * j;
        const int row = idx >> 4;
        const int c4 = (idx & 15) * 4;
        float4 v = *(const float4*)(Sp + (size_t)row * HD + c4);
        uint2 o;
        o.x = packh2(v.x, v.y);
        o.y = packh2(v.z, v.w);
        *(uint2*)&Sph[row][c4] = o;
    }
    if (tid < HD) zp[tid] = g_KS[(bh * NCHUNK + c) * HD + tid];
    __syncthreads();

    const uint32_t aRow = w * 16 + (l & 15);
    const uint32_t aK = (l >> 4) * 8;
    const uint32_t bRow = (l & 7) + ((l >> 4) << 3);
    const uint32_t bK = ((l >> 3) & 1) * 8;
    const int tRowB = ((l >> 3) & 1) * 8 + (l & 7);
    const int tColB = (l >> 4) * 8;

    // Phase 1: S = Q K^T
    float accS[8][4];
    #pragma unroll
    for (int i = 0; i < 8; i++)
        #pragma unroll
        for (int q = 0; q < 4; q++) accS[i][q] = 0.f;

    #pragma unroll
    for (int kk = 0; kk < 4; kk++) {
        uint32_t a[4];
        LDSM_X4(a[0], a[1], a[2], a[3], smem_u32(&Qs[aRow][kk * 16 + aK]));
        #pragma unroll
        for (int gN = 0; gN < 4; gN++) {
            uint32_t r0, r1, r2, r3;
            LDSM_X4(r0, r1, r2, r3, smem_u32(&Ks[gN * 16 + bRow][kk * 16 + bK]));
            MMA16816F16(accS[2 * gN],     a, r0, r1);
            MMA16816F16(accS[2 * gN + 1], a, r2, r3);
        }
    }

    const int row0 = w * 16 + (l >> 2);
    const int row1 = row0 + 8;
    float sum0 = 0.f, sum1 = 0.f;
    #pragma unroll
    for (int nf = 0; nf < 8; nf++) {
        #pragma unroll
        for (int jj = 0; jj < 2; jj++) {
            const int col = nf * 8 + 2 * (l & 3) + jj;
            accS[nf][jj]     = (col <= row0) ? accS[nf][jj]     : 0.f;
            accS[nf][2 + jj] = (col <= row1) ? accS[nf][2 + jj] : 0.f;
            sum0 += accS[nf][jj];
            sum1 += accS[nf][2 + jj];
        }
    }
    sum0 += __shfl_xor_sync(0xFFFFFFFF, sum0, 1);
    sum0 += __shfl_xor_sync(0xFFFFFFFF, sum0, 2);
    sum1 += __shfl_xor_sync(0xFFFFFFFF, sum1, 1);
    sum1 += __shfl_xor_sync(0xFFFFFFFF, sum1, 2);
    if ((l & 3) == 0) { rs[row0] = sum0; rs[row1] = sum1; }
    __syncthreads();
    if (tid < CHUNK) {
        float qz = 0.f;
        #pragma unroll 8
        for (int d = 0; d < HD; d++) qz = fmaf(__half2float(Qs[tid][d]), zp[d], qz);
        den[tid] = rs[tid] + qz + 1e-6f;
    }
    __syncthreads();

    // Phase 2: O = S V + Q S_prev
    float accO[8][4];
    #pragma unroll
    for (int i = 0; i < 8; i++)
        #pragma unroll
        for (int q = 0; q < 4; q++) accO[i][q] = 0.f;

    #pragma unroll
    for (int kk = 0; kk < 4; kk++) {
        uint32_t a[4];
        a[0] = packh2(accS[2 * kk][0],     accS[2 * kk][1]);
        a[1] = packh2(accS[2 * kk][2],     accS[2 * kk][3]);
        a[2] = packh2(accS[2 * kk + 1][0], accS[2 * kk + 1][1]);
        a[3] = packh2(accS[2 * kk + 1][2], accS[2 * kk + 1][3]);
        #pragma unroll
        for (int gN = 0; gN < 4; gN++) {
            uint32_t r0, r1, r2, r3;
            LDSM_X4_T(r0, r1, r2, r3,
                      smem_u32(&Vs[kk * 16 + tRowB][gN * 16 + tColB]));
            MMA16816F16(accO[2 * gN],     a, r0, r1);
            MMA16816F16(accO[2 * gN + 1], a, r2, r3);
        }
    }
    #pragma unroll
    for (int kk = 0; kk < 4; kk++) {
        uint32_t a[4];
        LDSM_X4(a[0], a[1], a[2], a[3], smem_u32(&Qs[aRow][kk * 16 + aK]));
        #pragma unroll
        for (int gN = 0; gN < 4; gN++) {
            uint32_t r0, r1, r2, r3;
            LDSM_X4_T(r0, r1, r2, r3,
                      smem_u32(&Sph[kk * 16 + tRowB][gN * 16 + tColB]));
            MMA16816F16(accO[2 * gN],     a, r0, r1);
            MMA16816F16(accO[2 * gN + 1], a, r2, r3);
        }
    }

    const float inv0 = 1.0f / den[row0];
    const float inv1 = 1.0f / den[row1];
    #pragma unroll
    for (int nf = 0; nf < 8; nf++) {
        const int col = nf * 8 + 2 * (l & 3);
        *(uint32_t*)(g_valh + rowbase + (size_t)row0 * DD + col) =
            packh2(accO[nf][0] * inv0, accO[nf][1] * inv0);
        *(uint32_t*)(g_valh + rowbase + (size_t)row1 * DD + col) =
            packh2(accO[nf][2] * inv1, accO[nf][3] * inv1);
    }
}

// ---------------------------------------------------------------------------
extern "C" void kernel_launch(void* const* d_in, const int* in_sizes, int n_in,
                              void* d_out, int out_size)
{
    (void)in_sizes; (void)n_in; (void)out_size;
    const float* x  = (const float*)d_in[0];
    const float* Wq = (const float*)d_in[2];
    const float* bq = (const float*)d_in[3];
    const float* Wk = (const float*)d_in[4];
    const float* bk = (const float*)d_in[5];
    const float* Wv = (const float*)d_in[6];
    const float* bv = (const float*)d_in[7];
    const float* Wo = (const float*)d_in[8];
    const float* bo = (const float*)d_in[9];
    float* out = (float*)d_out;

    __half *pxh, *pvalh, *pwT;
    cudaGetSymbolAddress((void**)&pxh,   g_xh);
    cudaGetSymbolAddress((void**)&pvalh, g_valh);
    cudaGetSymbolAddress((void**)&pwT,   g_wT);

    const int smbytes_g = 3 * 2 * 128 * 80;   // 61440
    cudaFuncSetAttribute(qkv_gemm_k, cudaFuncAttributeMaxDynamicSharedMemorySize, smbytes_g);
    cudaFuncSetAttribute(out_gemm_k, cudaFuncAttributeMaxDynamicSharedMemorySize, smbytes_g);

    // convert inputs to fp16
    const int n8 = MTOT * DD / 8;
    convh_k<<<1184, 256>>>((const float4*)x, (uint4*)pxh, n8);
    dim3 tgrid(DD / 32, DD / 32, 4), tblk(32, 8);
    convT_k<<<tgrid, tblk>>>(Wq, Wk, Wv, Wo, pwT);

    // fused Q/K/V projections
    qkv_gemm_k<<<dim3(3 * DD / 128, MTOT / 128), 256, smbytes_g>>>(pxh, pwT, bq, bk, bv);

    // linear attention (tensor-core passes)
    dim3 agrid(NCHUNK, NBH);
    kv_chunk_tc<<<agrid, 128>>>();
    prefix_k<<<NBH, 1024>>>();
    attn_out_tc<<<agrid, 128>>>();

    // output projection -> fp32 out
    out_gemm_k<<<dim3(DD / 128, MTOT / 128), 256, smbytes_g>>>(
        pvalh, pwT + 3 * (size_t)DD * DD, bo, out);
}

// round 8
// speedup vs baseline: 5.9262x; 1.0473x over previous
#include <cuda_runtime.h>
#include <cuda_fp16.h>
#include <cstdint>

// Problem constants (fixed by reference: B=4, S=2048, D=1024, H=16)
#define DD     1024
#define NH     16
#define HD     64
#define BATCH  4
#define SEQ    2048
#define MTOT   (BATCH * SEQ)      // 8192
#define CHUNK  64
#define NCHUNK (SEQ / CHUNK)      // 32
#define NBH    (BATCH * NH)       // 64
#define LDT    72                 // smem halves per tile row (64 + 8 pad)

// ---------------- scratch (allocation-free rule: __device__ globals) -------
__device__ __half g_KVh[NBH * NCHUNK * HD * HD];   // chunk KV -> exclusive prefix (fp16)
__device__ float  g_KS [NBH * NCHUNK * HD];

__device__ __half g_xh  [MTOT * DD];     // x in fp16
__device__ __half g_qh  [MTOT * DD];     // phi(xWq+b)
__device__ __half g_kh  [MTOT * DD];     // phi(xWk+b)
__device__ __half g_vh  [MTOT * DD];     // xWv+b
__device__ __half g_valh[MTOT * DD];     // attention output (fp16)
__device__ __half g_wT  [4][DD * DD];    // W^T fp16 (layout [N][K])

// ---------------------------------------------------------------------------
// PTX helpers (compute_100-safe: mma.sync / ldmatrix / cp.async only)
// ---------------------------------------------------------------------------
__device__ __forceinline__ uint32_t smem_u32(const void* p) {
    uint32_t a;
    asm("{ .reg .u64 t; cvta.to.shared.u64 t, %1; cvt.u32.u64 %0, t; }" : "=r"(a) : "l"(p));
    return a;
}

#define CP_ASYNC16(dst_u32, src_gptr) \
    asm volatile("cp.async.cg.shared.global [%0], [%1], 16;" \
                 :: "r"(dst_u32), "l"(src_gptr) : "memory")
#define CP_COMMIT() asm volatile("cp.async.commit_group;" ::: "memory")
#define CP_WAIT(n)  asm volatile("cp.async.wait_group %0;" :: "n"(n) : "memory")

#define LDSM_X4(r0, r1, r2, r3, addr) \
    asm volatile("ldmatrix.sync.aligned.m8n8.x4.shared.b16 {%0,%1,%2,%3}, [%4];" \
                 : "=r"(r0), "=r"(r1), "=r"(r2), "=r"(r3) : "r"(addr))

#define LDSM_X4_T(r0, r1, r2, r3, addr) \
    asm volatile("ldmatrix.sync.aligned.m8n8.x4.trans.shared.b16 {%0,%1,%2,%3}, [%4];" \
                 : "=r"(r0), "=r"(r1), "=r"(r2), "=r"(r3) : "r"(addr))

#define MMA16816F16(d, a, b0v, b1v) \
    asm volatile("mma.sync.aligned.m16n8k16.row.col.f32.f16.f16.f32 " \
                 "{%0,%1,%2,%3}, {%4,%5,%6,%7}, {%8,%9}, {%0,%1,%2,%3};" \
                 : "+f"((d)[0]), "+f"((d)[1]), "+f"((d)[2]), "+f"((d)[3]) \
                 : "r"((a)[0]), "r"((a)[1]), "r"((a)[2]), "r"((a)[3]), \
                   "r"(b0v), "r"(b1v))

__device__ __forceinline__ uint32_t packh2(float x, float y) {
    __half2 h = __floats2half2_rn(x, y);
    return *(uint32_t*)&h;
}

// ---------------------------------------------------------------------------
// Merged conversion kernel: blocks [0, NCVH) do x fp32->fp16; the rest do the
// four weight transposes+converts. One launch, both parts run concurrently.
// ---------------------------------------------------------------------------
#define NCVH 1184
__global__ __launch_bounds__(256)
void conv_all_k(const float4* __restrict__ x, uint4* __restrict__ xh, int n8,
                const float* __restrict__ W0, const float* __restrict__ W1,
                const float* __restrict__ W2, const float* __restrict__ W3,
                __half* __restrict__ hTbase)
{
    __shared__ float t[32][33];
    const int tid = threadIdx.x;
    if (blockIdx.x < NCVH) {
        for (int i = blockIdx.x * 256 + tid; i < n8; i += NCVH * 256) {
            float4 a = x[2 * i];
            float4 b = x[2 * i + 1];
            uint4 o;
            o.x = packh2(a.x, a.y);
            o.y = packh2(a.z, a.w);
            o.z = packh2(b.x, b.y);
            o.w = packh2(b.z, b.w);
            xh[i] = o;
        }
    } else {
        const int bidx = blockIdx.x - NCVH;        // 0..4095
        const int z = bidx >> 10;
        const int rem = bidx & 1023;
        const int n0 = (rem & 31) * 32, k0 = (rem >> 5) * 32;
        const float* W = (z == 0) ? W0 : (z == 1) ? W1 : (z == 2) ? W2 : W3;
        __half* hT = hTbase + (size_t)z * DD * DD;
        const int tx = tid & 31, ty = tid >> 5;    // 32 x 8
        #pragma unroll
        for (int r = ty; r < 32; r += 8)
            t[r][tx] = W[(size_t)(k0 + r) * DD + n0 + tx];
        __syncthreads();
        #pragma unroll
        for (int r = ty; r < 32; r += 8)
            hT[(size_t)(n0 + r) * DD + k0 + tx] = __float2half_rn(t[tx][r]);
    }
}

// ---------------------------------------------------------------------------
// fp16 tensor-core GEMM mainloop body
// CTA tile 128x128, BK=32, 8 warps (warp tile 64x32), 3-stage cp.async,
// single __syncthreads per k-iteration, 2 CTAs/SM.
// ---------------------------------------------------------------------------
struct GemmCoords {
    int wm, wn, lane;
    uint32_t aOff, bOff;
    int c0row, c0k, c1row, c1k;
};

__device__ __forceinline__ GemmCoords gemm_coords(int tid) {
    GemmCoords g;
    const int wid = tid >> 5;
    g.lane = tid & 31;
    g.wm = wid & 1;
    g.wn = wid >> 1;
    g.aOff = (uint32_t)(g.wm * 64 + (g.lane & 15)) * 80 + (uint32_t)(g.lane >> 4) * 16;
    g.bOff = (uint32_t)(g.wn * 32 + (g.lane & 7) + ((g.lane >> 4) << 3)) * 80
           + (uint32_t)((g.lane >> 3) & 1) * 16;
    g.c0row = tid >> 2;         g.c0k = tid & 3;
    g.c1row = (tid + 256) >> 2; g.c1k = (tid + 256) & 3;
    return g;
}

template<int HALF_OUT>
__device__ __forceinline__
void gemm_body(const GemmCoords& g, uint32_t sb, uint64_t gA, uint64_t gB,
               int m0, int n0, bool act, const float* bias, void* Cg)
{
    constexpr int SROWB = 80, TILEB = 128 * SROWB, STAGEB = 2 * TILEB;
    constexpr int NIT = DD / 32;

    float acc[4][4][4];
    #pragma unroll
    for (int i = 0; i < 4; i++)
        #pragma unroll
        for (int j = 0; j < 4; j++)
            #pragma unroll
            for (int q = 0; q < 4; q++) acc[i][j][q] = 0.f;

    auto load_stage = [&](int slot, int kc) {
        const uint32_t sbase = sb + slot * STAGEB;
        {
            const uint32_t doff = g.c0row * SROWB + g.c0k * 16;
            const uint64_t oa = ((size_t)(m0 + g.c0row) * DD + kc + g.c0k * 8) * 2;
            const uint64_t ob = ((size_t)(n0 + g.c0row) * DD + kc + g.c0k * 8) * 2;
            CP_ASYNC16(sbase + doff, gA + oa);
            CP_ASYNC16(sbase + TILEB + doff, gB + ob);
        }
        {
            const uint32_t doff = g.c1row * SROWB + g.c1k * 16;
            const uint64_t oa = ((size_t)(m0 + g.c1row) * DD + kc + g.c1k * 8) * 2;
            const uint64_t ob = ((size_t)(n0 + g.c1row) * DD + kc + g.c1k * 8) * 2;
            CP_ASYNC16(sbase + doff, gA + oa);
            CP_ASYNC16(sbase + TILEB + doff, gB + ob);
        }
    };

    load_stage(0, 0);  CP_COMMIT();
    load_stage(1, 32); CP_COMMIT();

    for (int it = 0; it < NIT; it++) {
        if (it + 1 < NIT) { CP_WAIT(1); } else { CP_WAIT(0); }
        __syncthreads();
        if (it + 2 < NIT) { load_stage((it + 2) % 3, (it + 2) * 32); CP_COMMIT(); }

        const int slot = it % 3;
        const uint32_t sA = sb + slot * STAGEB;
        const uint32_t sB = sA + TILEB;

        #pragma unroll
        for (int k16 = 0; k16 < 2; k16++) {
            const uint32_t kb = k16 * 32;
            uint32_t ah[4][4];
            #pragma unroll
            for (int mf = 0; mf < 4; mf++) {
                const uint32_t ao = g.aOff + mf * 16 * SROWB + kb;
                LDSM_X4(ah[mf][0], ah[mf][1], ah[mf][2], ah[mf][3], sA + ao);
            }
            uint32_t bb[2][4];
            #pragma unroll
            for (int gg = 0; gg < 2; gg++) {
                const uint32_t bo = g.bOff + gg * 16 * SROWB + kb;
                LDSM_X4(bb[gg][0], bb[gg][1], bb[gg][2], bb[gg][3], sB + bo);
            }
            #pragma unroll
            for (int mf = 0; mf < 4; mf++) {
                #pragma unroll
                for (int nf = 0; nf < 4; nf++) {
                    const int gg = nf >> 1, p = (nf & 1) * 2;
                    MMA16816F16(acc[mf][nf], ah[mf], bb[gg][p], bb[gg][p + 1]);
                }
            }
        }
    }

    #pragma unroll
    for (int nf = 0; nf < 4; nf++) {
        const int cg = n0 + g.wn * 32 + nf * 8 + (g.lane & 3) * 2;
        const float b0 = __ldg(&bias[cg]);
        const float b1 = __ldg(&bias[cg + 1]);
        #pragma unroll
        for (int mf = 0; mf < 4; mf++) {
            const int rg = m0 + g.wm * 64 + mf * 16 + (g.lane >> 2);
            float v0 = acc[mf][nf][0] + b0;
            float v1 = acc[mf][nf][1] + b1;
            float v2 = acc[mf][nf][2] + b0;
            float v3 = acc[mf][nf][3] + b1;
            if (act) {
                v0 = (v0 > 0.f) ? (v0 + 1.f) : __expf(v0);
                v1 = (v1 > 0.f) ? (v1 + 1.f) : __expf(v1);
                v2 = (v2 > 0.f) ? (v2 + 1.f) : __expf(v2);
                v3 = (v3 > 0.f) ? (v3 + 1.f) : __expf(v3);
            }
            if (HALF_OUT) {
                __half* Ch = (__half*)Cg;
                *(__half2*)(Ch + (size_t)rg * DD + cg)       = __floats2half2_rn(v0, v1);
                *(__half2*)(Ch + (size_t)(rg + 8) * DD + cg) = __floats2half2_rn(v2, v3);
            } else {
                float* Cf = (float*)Cg;
                *(float2*)(Cf + (size_t)rg * DD + cg)       = make_float2(v0, v1);
                *(float2*)(Cf + (size_t)(rg + 8) * DD + cg) = make_float2(v2, v3);
            }
        }
    }
}

// Fused Q/K/V projections: grid.x = 3*8 (which*8 + nblk), grid.y = M/128
__global__ __launch_bounds__(256, 2)
void qkv_gemm_k(const __half* __restrict__ A, const __half* __restrict__ wT,
                const float* __restrict__ bq, const float* __restrict__ bk,
                const float* __restrict__ bv)
{
    extern __shared__ char smem[];
    const int which = blockIdx.x >> 3;
    const int n0 = (blockIdx.x & 7) * 128;
    const int m0 = blockIdx.y * 128;
    const __half* BT = wT + (size_t)which * DD * DD;
    const float* bias = (which == 0) ? bq : (which == 1) ? bk : bv;
    __half* out = (which == 0) ? g_qh : (which == 1) ? g_kh : g_vh;
    GemmCoords g = gemm_coords(threadIdx.x);
    gemm_body<1>(g, smem_u32(smem), __cvta_generic_to_global(A),
                 __cvta_generic_to_global(BT), m0, n0, which < 2, bias, out);
}

// Output projection: fp16 A, fp32 C
__global__ __launch_bounds__(256, 2)
void out_gemm_k(const __half* __restrict__ A, const __half* __restrict__ BT,
                const float* __restrict__ bias, float* __restrict__ Cg)
{
    extern __shared__ char smem[];
    GemmCoords g = gemm_coords(threadIdx.x);
    gemm_body<0>(g, smem_u32(smem), __cvta_generic_to_global(A),
                 __cvta_generic_to_global(BT), blockIdx.y * 128, blockIdx.x * 128,
                 false, bias, Cg);
}

// ---------------------------------------------------------------------------
// Tile loaders: 64x64 fp16 -> smem [64][LDT]; row strides DD and HD
// ---------------------------------------------------------------------------
__device__ __forceinline__
void load_tile_h(__half (*dst)[LDT], const __half* src, size_t rowbase, int tid)
{
    #pragma unroll
    for (int j = 0; j < 4; j++) {
        const int idx = tid + 128 * j;
        const int row = idx >> 3;
        const int c = (idx & 7) * 8;
        *(uint4*)&dst[row][c] = *(const uint4*)(src + rowbase + (size_t)row * DD + c);
    }
}
__device__ __forceinline__
void load_tile_s(__half (*dst)[LDT], const __half* src, int tid)
{
    #pragma unroll
    for (int j = 0; j < 4; j++) {
        const int idx = tid + 128 * j;
        const int row = idx >> 3;
        const int c = (idx & 7) * 8;
        *(uint4*)&dst[row][c] = *(const uint4*)(src + (size_t)row * HD + c);
    }
}

// ---------------------------------------------------------------------------
// Pass A (tensor core): KV_c[d][m] = sum_t K[t][d] V[t][m] (fp16 out);
// ks_c[d] = sum_t K[t][d] (fp32)
// ---------------------------------------------------------------------------
__global__ __launch_bounds__(128)
void kv_chunk_tc()
{
    __shared__ __half Ks[CHUNK][LDT];
    __shared__ __half Vs[CHUNK][LDT];

    const int c = blockIdx.x, bh = blockIdx.y;
    const int b = bh >> 4, h = bh & 15;
    const int tid = threadIdx.x;
    const int w = tid >> 5, l = tid & 31;
    const size_t rowbase = (size_t)(b * SEQ + c * CHUNK) * DD + h * HD;

    load_tile_h(Ks, g_kh, rowbase, tid);
    load_tile_h(Vs, g_vh, rowbase, tid);
    __syncthreads();

    const int tRow = ((l >> 4) << 3) + (l & 7);
    const int tColA = ((l >> 3) & 1) * 8;
    const int tRowB = ((l >> 3) & 1) * 8 + (l & 7);
    const int tColB = (l >> 4) * 8;

    float acc[8][4];
    #pragma unroll
    for (int i = 0; i < 8; i++)
        #pragma unroll
        for (int q = 0; q < 4; q++) acc[i][q] = 0.f;

    #pragma unroll
    for (int kk = 0; kk < 4; kk++) {
        uint32_t a[4];
        LDSM_X4_T(a[0], a[1], a[2], a[3],
                  smem_u32(&Ks[kk * 16 + tRow][w * 16 + tColA]));
        #pragma unroll
        for (int gN = 0; gN < 4; gN++) {
            uint32_t r0, r1, r2, r3;
            LDSM_X4_T(r0, r1, r2, r3,
                      smem_u32(&Vs[kk * 16 + tRowB][gN * 16 + tColB]));
            MMA16816F16(acc[2 * gN],     a, r0, r1);
            MMA16816F16(acc[2 * gN + 1], a, r2, r3);
        }
    }

    __half* outp = g_KVh + (size_t)(bh * NCHUNK + c) * HD * HD;
    const int r0 = w * 16 + (l >> 2);
    #pragma unroll
    for (int nf = 0; nf < 8; nf++) {
        const int col = nf * 8 + 2 * (l & 3);
        *(uint32_t*)(outp + (size_t)r0 * HD + col)       = packh2(acc[nf][0], acc[nf][1]);
        *(uint32_t*)(outp + (size_t)(r0 + 8) * HD + col) = packh2(acc[nf][2], acc[nf][3]);
    }

    if (tid < HD) {
        float s = 0.f;
        #pragma unroll 8
        for (int t = 0; t < CHUNK; t++) s += __half2float(Ks[t][tid]);
        g_KS[(bh * NCHUNK + c) * HD + tid] = s;
    }
}

// ---------------------------------------------------------------------------
// Pass B: in-place EXCLUSIVE prefix over chunks. 8 CTAs per bh; each thread
// owns one half2 lane and scans the 32 chunks (fp32 accumulation).
// ---------------------------------------------------------------------------
__global__ __launch_bounds__(256)
void prefix_k()
{
    const int bh = blockIdx.x >> 3;
    const int pos = (blockIdx.x & 7) * 256 + threadIdx.x;   // 0..2047 half2 lanes
    __half* base = g_KVh + (size_t)bh * NCHUNK * HD * HD + pos * 2;
    float rx = 0.f, ry = 0.f;
    #pragma unroll 4
    for (int c = 0; c < NCHUNK; c++) {
        uint32_t* p = (uint32_t*)(base + (size_t)c * HD * HD);
        uint32_t v = *p;
        float2 f = __half22float2(*(__half2*)&v);
        *p = packh2(rx, ry);
        rx += f.x; ry += f.y;
    }
    if ((blockIdx.x & 7) == 0 && threadIdx.x < HD) {
        float r = 0.f;
        float* zb = g_KS + (size_t)bh * NCHUNK * HD + threadIdx.x;
        #pragma unroll 4
        for (int c = 0; c < NCHUNK; c++) {
            float v = zb[(size_t)c * HD];
            zb[(size_t)c * HD] = r;
            r += v;
        }
    }
}

// ---------------------------------------------------------------------------
// Pass C (tensor core): out = (tril(QK^T) V + Q S_prev) / (rowsum + Q.z + eps)
// ---------------------------------------------------------------------------
__global__ __launch_bounds__(128)
void attn_out_tc()
{
    __shared__ __half Qs [CHUNK][LDT];
    __shared__ __half Ks [CHUNK][LDT];
    __shared__ __half Vs [CHUNK][LDT];
    __shared__ __half Sph[HD][LDT];
    __shared__ float rs[CHUNK], den[CHUNK], zp[HD];

    const int c = blockIdx.x, bh = blockIdx.y;
    const int b = bh >> 4, h = bh & 15;
    const int tid = threadIdx.x;
    const int w = tid >> 5, l = tid & 31;
    const size_t rowbase = (size_t)(b * SEQ + c * CHUNK) * DD + h * HD;
    const __half* Sp = g_KVh + (size_t)(bh * NCHUNK + c) * HD * HD;

    load_tile_h(Qs, g_qh, rowbase, tid);
    load_tile_h(Ks, g_kh, rowbase, tid);
    load_tile_h(Vs, g_vh, rowbase, tid);
    load_tile_s(Sph, Sp, tid);
    if (tid < HD) zp[tid] = g_KS[(bh * NCHUNK + c) * HD + tid];
    __syncthreads();

    const uint32_t aRow = w * 16 + (l & 15);
    const uint32_t aK = (l >> 4) * 8;
    const uint32_t bRow = (l & 7) + ((l >> 4) << 3);
    const uint32_t bK = ((l >> 3) & 1) * 8;
    const int tRowB = ((l >> 3) & 1) * 8 + (l & 7);
    const int tColB = (l >> 4) * 8;

    // Phase 1: S = Q K^T
    float accS[8][4];
    #pragma unroll
    for (int i = 0; i < 8; i++)
        #pragma unroll
        for (int q = 0; q < 4; q++) accS[i][q] = 0.f;

    #pragma unroll
    for (int kk = 0; kk < 4; kk++) {
        uint32_t a[4];
        LDSM_X4(a[0], a[1], a[2], a[3], smem_u32(&Qs[aRow][kk * 16 + aK]));
        #pragma unroll
        for (int gN = 0; gN < 4; gN++) {
            uint32_t r0, r1, r2, r3;
            LDSM_X4(r0, r1, r2, r3, smem_u32(&Ks[gN * 16 + bRow][kk * 16 + bK]));
            MMA16816F16(accS[2 * gN],     a, r0, r1);
            MMA16816F16(accS[2 * gN + 1], a, r2, r3);
        }
    }

    const int row0 = w * 16 + (l >> 2);
    const int row1 = row0 + 8;
    float sum0 = 0.f, sum1 = 0.f;
    #pragma unroll
    for (int nf = 0; nf < 8; nf++) {
        #pragma unroll
        for (int jj = 0; jj < 2; jj++) {
            const int col = nf * 8 + 2 * (l & 3) + jj;
            accS[nf][jj]     = (col <= row0) ? accS[nf][jj]     : 0.f;
            accS[nf][2 + jj] = (col <= row1) ? accS[nf][2 + jj] : 0.f;
            sum0 += accS[nf][jj];
            sum1 += accS[nf][2 + jj];
        }
    }
    sum0 += __shfl_xor_sync(0xFFFFFFFF, sum0, 1);
    sum0 += __shfl_xor_sync(0xFFFFFFFF, sum0, 2);
    sum1 += __shfl_xor_sync(0xFFFFFFFF, sum1, 1);
    sum1 += __shfl_xor_sync(0xFFFFFFFF, sum1, 2);
    if ((l & 3) == 0) { rs[row0] = sum0; rs[row1] = sum1; }
    __syncthreads();
    if (tid < CHUNK) {
        float qz = 0.f;
        #pragma unroll 8
        for (int d = 0; d < HD; d++) qz = fmaf(__half2float(Qs[tid][d]), zp[d], qz);
        den[tid] = rs[tid] + qz + 1e-6f;
    }
    __syncthreads();

    // Phase 2: O = S V + Q S_prev
    float accO[8][4];
    #pragma unroll
    for (int i = 0; i < 8; i++)
        #pragma unroll
        for (int q = 0; q < 4; q++) accO[i][q] = 0.f;

    #pragma unroll
    for (int kk = 0; kk < 4; kk++) {
        uint32_t a[4];
        a[0] = packh2(accS[2 * kk][0],     accS[2 * kk][1]);
        a[1] = packh2(accS[2 * kk][2],     accS[2 * kk][3]);
        a[2] = packh2(accS[2 * kk + 1][0], accS[2 * kk + 1][1]);
        a[3] = packh2(accS[2 * kk + 1][2], accS[2 * kk + 1][3]);
        #pragma unroll
        for (int gN = 0; gN < 4; gN++) {
            uint32_t r0, r1, r2, r3;
            LDSM_X4_T(r0, r1, r2, r3,
                      smem_u32(&Vs[kk * 16 + tRowB][gN * 16 + tColB]));
            MMA16816F16(accO[2 * gN],     a, r0, r1);
            MMA16816F16(accO[2 * gN + 1], a, r2, r3);
        }
    }
    #pragma unroll
    for (int kk = 0; kk < 4; kk++) {
        uint32_t a[4];
        LDSM_X4(a[0], a[1], a[2], a[3], smem_u32(&Qs[aRow][kk * 16 + aK]));
        #pragma unroll
        for (int gN = 0; gN < 4; gN++) {
            uint32_t r0, r1, r2, r3;
            LDSM_X4_T(r0, r1, r2, r3,
                      smem_u32(&Sph[kk * 16 + tRowB][gN * 16 + tColB]));
            MMA16816F16(accO[2 * gN],     a, r0, r1);
            MMA16816F16(accO[2 * gN + 1], a, r2, r3);
        }
    }

    const float inv0 = 1.0f / den[row0];
    const float inv1 = 1.0f / den[row1];
    #pragma unroll
    for (int nf = 0; nf < 8; nf++) {
        const int col = nf * 8 + 2 * (l & 3);
        *(uint32_t*)(g_valh + rowbase + (size_t)row0 * DD + col) =
            packh2(accO[nf][0] * inv0, accO[nf][1] * inv0);
        *(uint32_t*)(g_valh + rowbase + (size_t)row1 * DD + col) =
            packh2(accO[nf][2] * inv1, accO[nf][3] * inv1);
    }
}

// ---------------------------------------------------------------------------
extern "C" void kernel_launch(void* const* d_in, const int* in_sizes, int n_in,
                              void* d_out, int out_size)
{
    (void)in_sizes; (void)n_in; (void)out_size;
    const float* x  = (const float*)d_in[0];
    const float* Wq = (const float*)d_in[2];
    const float* bq = (const float*)d_in[3];
    const float* Wk = (const float*)d_in[4];
    const float* bk = (const float*)d_in[5];
    const float* Wv = (const float*)d_in[6];
    const float* bv = (const float*)d_in[7];
    const float* Wo = (const float*)d_in[8];
    const float* bo = (const float*)d_in[9];
    float* out = (float*)d_out;

    __half *pxh, *pvalh, *pwT;
    cudaGetSymbolAddress((void**)&pxh,   g_xh);
    cudaGetSymbolAddress((void**)&pvalh, g_valh);
    cudaGetSymbolAddress((void**)&pwT,   g_wT);

    const int smbytes_g = 3 * 2 * 128 * 80;   // 61440
    cudaFuncSetAttribute(qkv_gemm_k, cudaFuncAttributeMaxDynamicSharedMemorySize, smbytes_g);
    cudaFuncSetAttribute(out_gemm_k, cudaFuncAttributeMaxDynamicSharedMemorySize, smbytes_g);

    // fp32->fp16 conversions (x + all 4 weight transposes, one launch)
    const int n8 = MTOT * DD / 8;
    conv_all_k<<<NCVH + 4096, 256>>>((const float4*)x, (uint4*)pxh, n8,
                                     Wq, Wk, Wv, Wo, pwT);

    // fused Q/K/V projections
    qkv_gemm_k<<<dim3(3 * DD / 128, MTOT / 128), 256, smbytes_g>>>(pxh, pwT, bq, bk, bv);

    // linear attention (tensor-core passes, fp16 state)
    dim3 agrid(NCHUNK, NBH);
    kv_chunk_tc<<<agrid, 128>>>();
    prefix_k<<<NBH * 8, 256>>>();
    attn_out_tc<<<agrid, 128>>>();

    // output projection -> fp32 out
    out_gemm_k<<<dim3(DD / 128, MTOT / 128), 256, smbytes_g>>>(
        pvalh, pwT + 3 * (size_t)DD * DD, bo, out);
}

// round 10
// speedup vs baseline: 6.1093x; 1.0309x over previous
#include <cuda_runtime.h>
#include <cuda_fp16.h>
#include <cstdint>

// Problem constants (fixed by reference: B=4, S=2048, D=1024, H=16)
#define DD     1024
#define NH     16
#define HD     64
#define BATCH  4
#define SEQ    2048
#define MTOT   (BATCH * SEQ)      // 8192
#define CHUNK  64
#define NCHUNK (SEQ / CHUNK)      // 32
#define NBH    (BATCH * NH)       // 64
#define LDT    72                 // smem halves per tile row (64 + 8 pad)

// ---------------- scratch (allocation-free rule: __device__ globals) -------
__device__ __half g_KVh[NBH * NCHUNK * HD * HD];   // chunk KV -> exclusive prefix (fp16)
__device__ float  g_KS [NBH * NCHUNK * HD];

__device__ __half g_xh  [MTOT * DD];     // x in fp16
__device__ __half g_qh  [MTOT * DD];     // phi(xWq+b)
__device__ __half g_kh  [MTOT * DD];     // phi(xWk+b)
__device__ __half g_vh  [MTOT * DD];     // xWv+b
__device__ __half g_valh[MTOT * DD];     // attention output (fp16)
__device__ __half g_wT  [4][DD * DD];    // W^T fp16 (layout [N][K])

// ---------------------------------------------------------------------------
// PTX helpers (compute_100-safe: mma.sync / ldmatrix / cp.async only)
// ---------------------------------------------------------------------------
__device__ __forceinline__ uint32_t smem_u32(const void* p) {
    uint32_t a;
    asm("{ .reg .u64 t; cvta.to.shared.u64 t, %1; cvt.u32.u64 %0, t; }" : "=r"(a) : "l"(p));
    return a;
}

#define CP_ASYNC16(dst_u32, src_gptr) \
    asm volatile("cp.async.cg.shared.global [%0], [%1], 16;" \
                 :: "r"(dst_u32), "l"(src_gptr) : "memory")
#define CP_COMMIT() asm volatile("cp.async.commit_group;" ::: "memory")
#define CP_WAIT(n)  asm volatile("cp.async.wait_group %0;" :: "n"(n) : "memory")

#define LDSM_X4(r0, r1, r2, r3, addr) \
    asm volatile("ldmatrix.sync.aligned.m8n8.x4.shared.b16 {%0,%1,%2,%3}, [%4];" \
                 : "=r"(r0), "=r"(r1), "=r"(r2), "=r"(r3) : "r"(addr))

#define LDSM_X4_T(r0, r1, r2, r3, addr) \
    asm volatile("ldmatrix.sync.aligned.m8n8.x4.trans.shared.b16 {%0,%1,%2,%3}, [%4];" \
                 : "=r"(r0), "=r"(r1), "=r"(r2), "=r"(r3) : "r"(addr))

#define MMA16816F16(d, a, b0v, b1v) \
    asm volatile("mma.sync.aligned.m16n8k16.row.col.f32.f16.f16.f32 " \
                 "{%0,%1,%2,%3}, {%4,%5,%6,%7}, {%8,%9}, {%0,%1,%2,%3};" \
                 : "+f"((d)[0]), "+f"((d)[1]), "+f"((d)[2]), "+f"((d)[3]) \
                 : "r"((a)[0]), "r"((a)[1]), "r"((a)[2]), "r"((a)[3]), \
                   "r"(b0v), "r"(b1v))

__device__ __forceinline__ uint32_t packh2(float x, float y) {
    __half2 h = __floats2half2_rn(x, y);
    return *(uint32_t*)&h;
}

// ---------------------------------------------------------------------------
// Merged conversion kernel: blocks [0, NCVH) do x fp32->fp16; the rest do the
// four weight transposes+converts. One launch, both parts run concurrently.
// ---------------------------------------------------------------------------
#define NCVH 1184
__global__ __launch_bounds__(256)
void conv_all_k(const float4* __restrict__ x, uint4* __restrict__ xh, int n8,
                const float* __restrict__ W0, const float* __restrict__ W1,
                const float* __restrict__ W2, const float* __restrict__ W3,
                __half* __restrict__ hTbase)
{
    __shared__ float t[32][33];
    const int tid = threadIdx.x;
    if (blockIdx.x < NCVH) {
        for (int i = blockIdx.x * 256 + tid; i < n8; i += NCVH * 256) {
            float4 a = x[2 * i];
            float4 b = x[2 * i + 1];
            uint4 o;
            o.x = packh2(a.x, a.y);
            o.y = packh2(a.z, a.w);
            o.z = packh2(b.x, b.y);
            o.w = packh2(b.z, b.w);
            xh[i] = o;
        }
    } else {
        const int bidx = blockIdx.x - NCVH;        // 0..4095
        const int z = bidx >> 10;
        const int rem = bidx & 1023;
        const int n0 = (rem & 31) * 32, k0 = (rem >> 5) * 32;
        const float* W = (z == 0) ? W0 : (z == 1) ? W1 : (z == 2) ? W2 : W3;
        __half* hT = hTbase + (size_t)z * DD * DD;
        const int tx = tid & 31, ty = tid >> 5;    // 32 x 8
        #pragma unroll
        for (int r = ty; r < 32; r += 8)
            t[r][tx] = W[(size_t)(k0 + r) * DD + n0 + tx];
        __syncthreads();
        #pragma unroll
        for (int r = ty; r < 32; r += 8)
            hT[(size_t)(n0 + r) * DD + k0 + tx] = __float2half_rn(t[tx][r]);
    }
}

// ---------------------------------------------------------------------------
// fp16 tensor-core GEMM mainloop body
// CTA tile 128x128, BK=32, 8 warps (warp tile 64x32), 3-stage cp.async,
// single __syncthreads per k-iteration, 2 CTAs/SM.
// ---------------------------------------------------------------------------
struct GemmCoords {
    int wm, wn, lane;
    uint32_t aOff, bOff;
    int c0row, c0k, c1row, c1k;
};

__device__ __forceinline__ GemmCoords gemm_coords(int tid) {
    GemmCoords g;
    const int wid = tid >> 5;
    g.lane = tid & 31;
    g.wm = wid & 1;
    g.wn = wid >> 1;
    g.aOff = (uint32_t)(g.wm * 64 + (g.lane & 15)) * 80 + (uint32_t)(g.lane >> 4) * 16;
    g.bOff = (uint32_t)(g.wn * 32 + (g.lane & 7) + ((g.lane >> 4) << 3)) * 80
           + (uint32_t)((g.lane >> 3) & 1) * 16;
    g.c0row = tid >> 2;         g.c0k = tid & 3;
    g.c1row = (tid + 256) >> 2; g.c1k = (tid + 256) & 3;
    return g;
}

template<int HALF_OUT>
__device__ __forceinline__
void gemm_body(const GemmCoords& g, uint32_t sb, uint64_t gA, uint64_t gB,
               int m0, int n0, bool act, const float* bias, void* Cg)
{
    constexpr int SROWB = 80, TILEB = 128 * SROWB, STAGEB = 2 * TILEB;
    constexpr int NIT = DD / 32;

    float acc[4][4][4];
    #pragma unroll
    for (int i = 0; i < 4; i++)
        #pragma unroll
        for (int j = 0; j < 4; j++)
            #pragma unroll
            for (int q = 0; q < 4; q++) acc[i][j][q] = 0.f;

    auto load_stage = [&](int slot, int kc) {
        const uint32_t sbase = sb + slot * STAGEB;
        {
            const uint32_t doff = g.c0row * SROWB + g.c0k * 16;
            const uint64_t oa = ((size_t)(m0 + g.c0row) * DD + kc + g.c0k * 8) * 2;
            const uint64_t ob = ((size_t)(n0 + g.c0row) * DD + kc + g.c0k * 8) * 2;
            CP_ASYNC16(sbase + doff, gA + oa);
            CP_ASYNC16(sbase + TILEB + doff, gB + ob);
        }
        {
            const uint32_t doff = g.c1row * SROWB + g.c1k * 16;
            const uint64_t oa = ((size_t)(m0 + g.c1row) * DD + kc + g.c1k * 8) * 2;
            const uint64_t ob = ((size_t)(n0 + g.c1row) * DD + kc + g.c1k * 8) * 2;
            CP_ASYNC16(sbase + doff, gA + oa);
            CP_ASYNC16(sbase + TILEB + doff, gB + ob);
        }
    };

    load_stage(0, 0);  CP_COMMIT();
    load_stage(1, 32); CP_COMMIT();

    for (int it = 0; it < NIT; it++) {
        if (it + 1 < NIT) { CP_WAIT(1); } else { CP_WAIT(0); }
        __syncthreads();
        if (it + 2 < NIT) { load_stage((it + 2) % 3, (it + 2) * 32); CP_COMMIT(); }

        const int slot = it % 3;
        const uint32_t sA = sb + slot * STAGEB;
        const uint32_t sB = sA + TILEB;

        #pragma unroll
        for (int k16 = 0; k16 < 2; k16++) {
            const uint32_t kb = k16 * 32;
            uint32_t ah[4][4];
            #pragma unroll
            for (int mf = 0; mf < 4; mf++) {
                const uint32_t ao = g.aOff + mf * 16 * SROWB + kb;
                LDSM_X4(ah[mf][0], ah[mf][1], ah[mf][2], ah[mf][3], sA + ao);
            }
            uint32_t bb[2][4];
            #pragma unroll
            for (int gg = 0; gg < 2; gg++) {
                const uint32_t bo = g.bOff + gg * 16 * SROWB + kb;
                LDSM_X4(bb[gg][0], bb[gg][1], bb[gg][2], bb[gg][3], sB + bo);
            }
            #pragma unroll
            for (int mf = 0; mf < 4; mf++) {
                #pragma unroll
                for (int nf = 0; nf < 4; nf++) {
                    const int gg = nf >> 1, p = (nf & 1) * 2;
                    MMA16816F16(acc[mf][nf], ah[mf], bb[gg][p], bb[gg][p + 1]);
                }
            }
        }
    }

    #pragma unroll
    for (int nf = 0; nf < 4; nf++) {
        const int cg = n0 + g.wn * 32 + nf * 8 + (g.lane & 3) * 2;
        const float b0 = __ldg(&bias[cg]);
        const float b1 = __ldg(&bias[cg + 1]);
        #pragma unroll
        for (int mf = 0; mf < 4; mf++) {
            const int rg = m0 + g.wm * 64 + mf * 16 + (g.lane >> 2);
            float v0 = acc[mf][nf][0] + b0;
            float v1 = acc[mf][nf][1] + b1;
            float v2 = acc[mf][nf][2] + b0;
            float v3 = acc[mf][nf][3] + b1;
            if (act) {
                v0 = (v0 > 0.f) ? (v0 + 1.f) : __expf(v0);
                v1 = (v1 > 0.f) ? (v1 + 1.f) : __expf(v1);
                v2 = (v2 > 0.f) ? (v2 + 1.f) : __expf(v2);
                v3 = (v3 > 0.f) ? (v3 + 1.f) : __expf(v3);
            }
            if (HALF_OUT) {
                __half* Ch = (__half*)Cg;
                *(__half2*)(Ch + (size_t)rg * DD + cg)       = __floats2half2_rn(v0, v1);
                *(__half2*)(Ch + (size_t)(rg + 8) * DD + cg) = __floats2half2_rn(v2, v3);
            } else {
                float* Cf = (float*)Cg;
                *(float2*)(Cf + (size_t)rg * DD + cg)       = make_float2(v0, v1);
                *(float2*)(Cf + (size_t)(rg + 8) * DD + cg) = make_float2(v2, v3);
            }
        }
    }
}

// Fused Q/K/V projections: grid.x = 3*8 (which*8 + nblk), grid.y = M/128
__global__ __launch_bounds__(256, 2)
void qkv_gemm_k(const __half* __restrict__ A, const __half* __restrict__ wT,
                const float* __restrict__ bq, const float* __restrict__ bk,
                const float* __restrict__ bv)
{
    extern __shared__ char smem[];
    const int which = blockIdx.x >> 3;
    const int n0 = (blockIdx.x & 7) * 128;
    const int m0 = blockIdx.y * 128;
    const __half* BT = wT + (size_t)which * DD * DD;
    const float* bias = (which == 0) ? bq : (which == 1) ? bk : bv;
    __half* out = (which == 0) ? g_qh : (which == 1) ? g_kh : g_vh;
    GemmCoords g = gemm_coords(threadIdx.x);
    gemm_body<1>(g, smem_u32(smem), __cvta_generic_to_global(A),
                 __cvta_generic_to_global(BT), m0, n0, which < 2, bias, out);
}

// Output projection: fp16 A, fp32 C
__global__ __launch_bounds__(256, 2)
void out_gemm_k(const __half* __restrict__ A, const __half* __restrict__ BT,
                const float* __restrict__ bias, float* __restrict__ Cg)
{
    extern __shared__ char smem[];
    GemmCoords g = gemm_coords(threadIdx.x);
    gemm_body<0>(g, smem_u32(smem), __cvta_generic_to_global(A),
                 __cvta_generic_to_global(BT), blockIdx.y * 128, blockIdx.x * 128,
                 false, bias, Cg);
}

// ---------------------------------------------------------------------------
// Async tile loaders: 64x64 fp16 -> smem [64][LDT] via cp.async (no register
// round-trip, full-tile MLP). Row strides DD (qkvh) and HD (prefix state).
// ---------------------------------------------------------------------------
__device__ __forceinline__
void load_tile_cp(uint32_t dst_s, const __half* src, size_t rowbase, int tid)
{
    #pragma unroll
    for (int j = 0; j < 4; j++) {
        const int idx = tid + 128 * j;
        const int row = idx >> 3;
        const int c = (idx & 7) * 8;
        CP_ASYNC16(dst_s + (uint32_t)(row * LDT + c) * 2,
                   (const void*)(src + rowbase + (size_t)row * DD + c));
    }
}
__device__ __forceinline__
void load_tile_cp_s(uint32_t dst_s, const __half* src, int tid)
{
    #pragma unroll
    for (int j = 0; j < 4; j++) {
        const int idx = tid + 128 * j;
        const int row = idx >> 3;
        const int c = (idx & 7) * 8;
        CP_ASYNC16(dst_s + (uint32_t)(row * LDT + c) * 2,
                   (const void*)(src + (size_t)row * HD + c));
    }
}

// ---------------------------------------------------------------------------
// Pass A (tensor core): KV_c[d][m] = sum_t K[t][d] V[t][m] (fp16 out);
// ks_c[d] = sum_t K[t][d] (fp32)
// ---------------------------------------------------------------------------
__global__ __launch_bounds__(128)
void kv_chunk_tc()
{
    __shared__ __half Ks[CHUNK][LDT];
    __shared__ __half Vs[CHUNK][LDT];

    const int c = blockIdx.x, bh = blockIdx.y;
    const int b = bh >> 4, h = bh & 15;
    const int tid = threadIdx.x;
    const int w = tid >> 5, l = tid & 31;
    const size_t rowbase = (size_t)(b * SEQ + c * CHUNK) * DD + h * HD;

    load_tile_cp(smem_u32(Ks), g_kh, rowbase, tid);
    load_tile_cp(smem_u32(Vs), g_vh, rowbase, tid);
    CP_COMMIT();
    CP_WAIT(0);
    __syncthreads();

    const int tRow = ((l >> 4) << 3) + (l & 7);
    const int tColA = ((l >> 3) & 1) * 8;
    const int tRowB = ((l >> 3) & 1) * 8 + (l & 7);
    const int tColB = (l >> 4) * 8;

    float acc[8][4];
    #pragma unroll
    for (int i = 0; i < 8; i++)
        #pragma unroll
        for (int q = 0; q < 4; q++) acc[i][q] = 0.f;

    #pragma unroll
    for (int kk = 0; kk < 4; kk++) {
        uint32_t a[4];
        LDSM_X4_T(a[0], a[1], a[2], a[3],
                  smem_u32(&Ks[kk * 16 + tRow][w * 16 + tColA]));
        #pragma unroll
        for (int gN = 0; gN < 4; gN++) {
            uint32_t r0, r1, r2, r3;
            LDSM_X4_T(r0, r1, r2, r3,
                      smem_u32(&Vs[kk * 16 + tRowB][gN * 16 + tColB]));
            MMA16816F16(acc[2 * gN],     a, r0, r1);
            MMA16816F16(acc[2 * gN + 1], a, r2, r3);
        }
    }

    __half* outp = g_KVh + (size_t)(bh * NCHUNK + c) * HD * HD;
    const int r0 = w * 16 + (l >> 2);
    #pragma unroll
    for (int nf = 0; nf < 8; nf++) {
        const int col = nf * 8 + 2 * (l & 3);
        *(uint32_t*)(outp + (size_t)r0 * HD + col)       = packh2(acc[nf][0], acc[nf][1]);
        *(uint32_t*)(outp + (size_t)(r0 + 8) * HD + col) = packh2(acc[nf][2], acc[nf][3]);
    }

    if (tid < HD) {
        float s = 0.f;
        #pragma unroll 8
        for (int t = 0; t < CHUNK; t++) s += __half2float(Ks[t][tid]);
        g_KS[(bh * NCHUNK + c) * HD + tid] = s;
    }
}

// ---------------------------------------------------------------------------
// Pass B: in-place EXCLUSIVE prefix over chunks. 8 CTAs per bh; each thread
// owns one half2 lane. All 32 chunk values preloaded into registers (MLP=32),
// scan in registers, then store — no serialized memory round-trips.
// ---------------------------------------------------------------------------
__global__ __launch_bounds__(256)
void prefix_k()
{
    const int bh = blockIdx.x >> 3;
    const int pos = (blockIdx.x & 7) * 256 + threadIdx.x;   // 0..2047 half2 lanes
    __half* base = g_KVh + (size_t)bh * NCHUNK * HD * HD + pos * 2;

    uint32_t v[NCHUNK];
    #pragma unroll
    for (int c = 0; c < NCHUNK; c++)
        v[c] = *(const uint32_t*)(base + (size_t)c * HD * HD);

    float rx = 0.f, ry = 0.f;
    #pragma unroll
    for (int c = 0; c < NCHUNK; c++) {
        float2 f = __half22float2(*(__half2*)&v[c]);
        *(uint32_t*)(base + (size_t)c * HD * HD) = packh2(rx, ry);
        rx += f.x; ry += f.y;
    }

    if ((blockIdx.x & 7) == 0 && threadIdx.x < HD) {
        float* zb = g_KS + (size_t)bh * NCHUNK * HD + threadIdx.x;
        float zv[NCHUNK];
        #pragma unroll
        for (int c = 0; c < NCHUNK; c++) zv[c] = zb[(size_t)c * HD];
        float r = 0.f;
        #pragma unroll
        for (int c = 0; c < NCHUNK; c++) {
            zb[(size_t)c * HD] = r;
            r += zv[c];
        }
    }
}

// ---------------------------------------------------------------------------
// Pass C (tensor core): out = (tril(QK^T) V + Q S_prev) / (rowsum + Q.z + eps)
// ---------------------------------------------------------------------------
__global__ __launch_bounds__(128)
void attn_out_tc()
{
    __shared__ __half Qs [CHUNK][LDT];
    __shared__ __half Ks [CHUNK][LDT];
    __shared__ __half Vs [CHUNK][LDT];
    __shared__ __half Sph[HD][LDT];
    __shared__ float rs[CHUNK], den[CHUNK], zp[HD];

    const int c = blockIdx.x, bh = blockIdx.y;
    const int b = bh >> 4, h = bh & 15;
    const int tid = threadIdx.x;
    const int w = tid >> 5, l = tid & 31;
    const size_t rowbase = (size_t)(b * SEQ + c * CHUNK) * DD + h * HD;
    const __half* Sp = g_KVh + (size_t)(bh * NCHUNK + c) * HD * HD;

    load_tile_cp(smem_u32(Qs), g_qh, rowbase, tid);
    load_tile_cp(smem_u32(Ks), g_kh, rowbase, tid);
    load_tile_cp(smem_u32(Vs), g_vh, rowbase, tid);
    load_tile_cp_s(smem_u32(Sph), Sp, tid);
    CP_COMMIT();
    if (tid < HD) zp[tid] = g_KS[(bh * NCHUNK + c) * HD + tid];
    CP_WAIT(0);
    __syncthreads();

    const uint32_t aRow = w * 16 + (l & 15);
    const uint32_t aK = (l >> 4) * 8;
    const uint32_t bRow = (l & 7) + ((l >> 4) << 3);
    const uint32_t bK = ((l >> 3) & 1) * 8;
    const int tRowB = ((l >> 3) & 1) * 8 + (l & 7);
    const int tColB = (l >> 4) * 8;

    // Phase 1: S = Q K^T
    float accS[8][4];
    #pragma unroll
    for (int i = 0; i < 8; i++)
        #pragma unroll
        for (int q = 0; q < 4; q++) accS[i][q] = 0.f;

    #pragma unroll
    for (int kk = 0; kk < 4; kk++) {
        uint32_t a[4];
        LDSM_X4(a[0], a[1], a[2], a[3], smem_u32(&Qs[aRow][kk * 16 + aK]));
        #pragma unroll
        for (int gN = 0; gN < 4; gN++) {
            uint32_t r0, r1, r2, r3;
            LDSM_X4(r0, r1, r2, r3, smem_u32(&Ks[gN * 16 + bRow][kk * 16 + bK]));
            MMA16816F16(accS[2 * gN],     a, r0, r1);
            MMA16816F16(accS[2 * gN + 1], a, r2, r3);
        }
    }

    const int row0 = w * 16 + (l >> 2);
    const int row1 = row0 + 8;
    float sum0 = 0.f, sum1 = 0.f;
    #pragma unroll
    for (int nf = 0; nf < 8; nf++) {
        #pragma unroll
        for (int jj = 0; jj < 2; jj++) {
            const int col = nf * 8 + 2 * (l & 3) + jj;
            accS[nf][jj]     = (col <= row0) ? accS[nf][jj]     : 0.f;
            accS[nf][2 + jj] = (col <= row1) ? accS[nf][2 + jj] : 0.f;
            sum0 += accS[nf][jj];
            sum1 += accS[nf][2 + jj];
        }
    }
    sum0 += __shfl_xor_sync(0xFFFFFFFF, sum0, 1);
    sum0 += __shfl_xor_sync(0xFFFFFFFF, sum0, 2);
    sum1 += __shfl_xor_sync(0xFFFFFFFF, sum1, 1);
    sum1 += __shfl_xor_sync(0xFFFFFFFF, sum1, 2);
    if ((l & 3) == 0) { rs[row0] = sum0; rs[row1] = sum1; }
    __syncthreads();
    if (tid < CHUNK) {
        float qz = 0.f;
        #pragma unroll 8
        for (int d = 0; d < HD; d++) qz = fmaf(__half2float(Qs[tid][d]), zp[d], qz);
        den[tid] = rs[tid] + qz + 1e-6f;
    }
    __syncthreads();

    // Phase 2: O = S V + Q S_prev
    float accO[8][4];
    #pragma unroll
    for (int i = 0; i < 8; i++)
        #pragma unroll
        for (int q = 0; q < 4; q++) accO[i][q] = 0.f;

    #pragma unroll
    for (int kk = 0; kk < 4; kk++) {
        uint32_t a[4];
        a[0] = packh2(accS[2 * kk][0],     accS[2 * kk][1]);
        a[1] = packh2(accS[2 * kk][2],     accS[2 * kk][3]);
        a[2] = packh2(accS[2 * kk + 1][0], accS[2 * kk + 1][1]);
        a[3] = packh2(accS[2 * kk + 1][2], accS[2 * kk + 1][3]);
        #pragma unroll
        for (int gN = 0; gN < 4; gN++) {
            uint32_t r0, r1, r2, r3;
            LDSM_X4_T(r0, r1, r2, r3,
                      smem_u32(&Vs[kk * 16 + tRowB][gN * 16 + tColB]));
            MMA16816F16(accO[2 * gN],     a, r0, r1);
            MMA16816F16(accO[2 * gN + 1], a, r2, r3);
        }
    }
    #pragma unroll
    for (int kk = 0; kk < 4; kk++) {
        uint32_t a[4];
        LDSM_X4(a[0], a[1], a[2], a[3], smem_u32(&Qs[aRow][kk * 16 + aK]));
        #pragma unroll
        for (int gN = 0; gN < 4; gN++) {
            uint32_t r0, r1, r2, r3;
            LDSM_X4_T(r0, r1, r2, r3,
                      smem_u32(&Sph[kk * 16 + tRowB][gN * 16 + tColB]));
            MMA16816F16(accO[2 * gN],     a, r0, r1);
            MMA16816F16(accO[2 * gN + 1], a, r2, r3);
        }
    }

    const float inv0 = 1.0f / den[row0];
    const float inv1 = 1.0f / den[row1];
    #pragma unroll
    for (int nf = 0; nf < 8; nf++) {
        const int col = nf * 8 + 2 * (l & 3);
        *(uint32_t*)(g_valh + rowbase + (size_t)row0 * DD + col) =
            packh2(accO[nf][0] * inv0, accO[nf][1] * inv0);
        *(uint32_t*)(g_valh + rowbase + (size_t)row1 * DD + col) =
            packh2(accO[nf][2] * inv1, accO[nf][3] * inv1);
    }
}

// ---------------------------------------------------------------------------
extern "C" void kernel_launch(void* const* d_in, const int* in_sizes, int n_in,
                              void* d_out, int out_size)
{
    (void)in_sizes; (void)n_in; (void)out_size;
    const float* x  = (const float*)d_in[0];
    const float* Wq = (const float*)d_in[2];
    const float* bq = (const float*)d_in[3];
    const float* Wk = (const float*)d_in[4];
    const float* bk = (const float*)d_in[5];
    const float* Wv = (const float*)d_in[6];
    const float* bv = (const float*)d_in[7];
    const float* Wo = (const float*)d_in[8];
    const float* bo = (const float*)d_in[9];
    float* out = (float*)d_out;

    __half *pxh, *pvalh, *pwT;
    cudaGetSymbolAddress((void**)&pxh,   g_xh);
    cudaGetSymbolAddress((void**)&pvalh, g_valh);
    cudaGetSymbolAddress((void**)&pwT,   g_wT);

    const int smbytes_g = 3 * 2 * 128 * 80;   // 61440
    cudaFuncSetAttribute(qkv_gemm_k, cudaFuncAttributeMaxDynamicSharedMemorySize, smbytes_g);
    cudaFuncSetAttribute(out_gemm_k, cudaFuncAttributeMaxDynamicSharedMemorySize, smbytes_g);

    // fp32->fp16 conversions (x + all 4 weight transposes, one launch)
    const int n8 = MTOT * DD / 8;
    conv_all_k<<<NCVH + 4096, 256>>>((const float4*)x, (uint4*)pxh, n8,
                                     Wq, Wk, Wv, Wo, pwT);

    // fused Q/K/V projections
    qkv_gemm_k<<<dim3(3 * DD / 128, MTOT / 128), 256, smbytes_g>>>(pxh, pwT, bq, bk, bv);

    // linear attention (tensor-core passes, fp16 state)
    dim3 agrid(NCHUNK, NBH);
    kv_chunk_tc<<<agrid, 128>>>();
    prefix_k<<<NBH * 8, 256>>>();
    attn_out_tc<<<agrid, 128>>>();

    // output projection -> fp32 out
    out_gemm_k<<<dim3(DD / 128, MTOT / 128), 256, smbytes_g>>>(
        pvalh, pwT + 3 * (size_t)DD * DD, bo, out);
}

// round 12
// speedup vs baseline: 6.4087x; 1.0490x over previous
#include <cuda_runtime.h>
#include <cuda_fp16.h>
#include <cstdint>

// Problem constants (fixed by reference: B=4, S=2048, D=1024, H=16)
#define DD     1024
#define NH     16
#define HD     64
#define BATCH  4
#define SEQ    2048
#define MTOT   (BATCH * SEQ)      // 8192
#define CHUNK  64
#define NCHUNK (SEQ / CHUNK)      // 32
#define NBH    (BATCH * NH)       // 64
#define LDT    72                 // smem halves per tile row (64 + 8 pad)

// ---------------- scratch (allocation-free rule: __device__ globals) -------
__device__ __half g_KVh[NBH * NCHUNK * HD * HD];   // chunk KV -> exclusive prefix (fp16)
__device__ float  g_KS [NBH * NCHUNK * HD];

__device__ __half g_xh  [MTOT * DD];     // x in fp16
__device__ __half g_qh  [MTOT * DD];     // phi(xWq+b)
__device__ __half g_kh  [MTOT * DD];     // phi(xWk+b)
__device__ __half g_vh  [MTOT * DD];     // xWv+b
__device__ __half g_valh[MTOT * DD];     // attention output (fp16)
__device__ __half g_wT  [4][DD * DD];    // W^T fp16 (layout [N][K])

// ---------------------------------------------------------------------------
// PTX helpers (compute_100-safe: mma.sync / ldmatrix / cp.async only)
// ---------------------------------------------------------------------------
__device__ __forceinline__ uint32_t smem_u32(const void* p) {
    uint32_t a;
    asm("{ .reg .u64 t; cvta.to.shared.u64 t, %1; cvt.u32.u64 %0, t; }" : "=r"(a) : "l"(p));
    return a;
}

#define CP_ASYNC16(dst_u32, src_gptr) \
    asm volatile("cp.async.cg.shared.global [%0], [%1], 16;" \
                 :: "r"(dst_u32), "l"(src_gptr) : "memory")
#define CP_COMMIT() asm volatile("cp.async.commit_group;" ::: "memory")
#define CP_WAIT(n)  asm volatile("cp.async.wait_group %0;" :: "n"(n) : "memory")

#define LDSM_X4(r0, r1, r2, r3, addr) \
    asm volatile("ldmatrix.sync.aligned.m8n8.x4.shared.b16 {%0,%1,%2,%3}, [%4];" \
                 : "=r"(r0), "=r"(r1), "=r"(r2), "=r"(r3) : "r"(addr))

#define LDSM_X4_T(r0, r1, r2, r3, addr) \
    asm volatile("ldmatrix.sync.aligned.m8n8.x4.trans.shared.b16 {%0,%1,%2,%3}, [%4];" \
                 : "=r"(r0), "=r"(r1), "=r"(r2), "=r"(r3) : "r"(addr))

#define MMA16816F16(d, a, b0v, b1v) \
    asm volatile("mma.sync.aligned.m16n8k16.row.col.f32.f16.f16.f32 " \
                 "{%0,%1,%2,%3}, {%4,%5,%6,%7}, {%8,%9}, {%0,%1,%2,%3};" \
                 : "+f"((d)[0]), "+f"((d)[1]), "+f"((d)[2]), "+f"((d)[3]) \
                 : "r"((a)[0]), "r"((a)[1]), "r"((a)[2]), "r"((a)[3]), \
                   "r"(b0v), "r"(b1v))

__device__ __forceinline__ uint32_t packh2(float x, float y) {
    __half2 h = __floats2half2_rn(x, y);
    return *(uint32_t*)&h;
}

// ---------------------------------------------------------------------------
// Merged conversion kernel: blocks [0, NCVH) do x fp32->fp16; the rest do the
// four weight transposes+converts. One launch, both parts run concurrently.
// ---------------------------------------------------------------------------
#define NCVH 1184
__global__ __launch_bounds__(256)
void conv_all_k(const float4* __restrict__ x, uint4* __restrict__ xh, int n8,
                const float* __restrict__ W0, const float* __restrict__ W1,
                const float* __restrict__ W2, const float* __restrict__ W3,
                __half* __restrict__ hTbase)
{
    __shared__ float t[32][33];
    const int tid = threadIdx.x;
    if (blockIdx.x < NCVH) {
        for (int i = blockIdx.x * 256 + tid; i < n8; i += NCVH * 256) {
            float4 a = x[2 * i];
            float4 b = x[2 * i + 1];
            uint4 o;
            o.x = packh2(a.x, a.y);
            o.y = packh2(a.z, a.w);
            o.z = packh2(b.x, b.y);
            o.w = packh2(b.z, b.w);
            xh[i] = o;
        }
    } else {
        const int bidx = blockIdx.x - NCVH;        // 0..4095
        const int z = bidx >> 10;
        const int rem = bidx & 1023;
        const int n0 = (rem & 31) * 32, k0 = (rem >> 5) * 32;
        const float* W = (z == 0) ? W0 : (z == 1) ? W1 : (z == 2) ? W2 : W3;
        __half* hT = hTbase + (size_t)z * DD * DD;
        const int tx = tid & 31, ty = tid >> 5;    // 32 x 8
        #pragma unroll
        for (int r = ty; r < 32; r += 8)
            t[r][tx] = W[(size_t)(k0 + r) * DD + n0 + tx];
        __syncthreads();
        #pragma unroll
        for (int r = ty; r < 32; r += 8)
            hT[(size_t)(n0 + r) * DD + k0 + tx] = __float2half_rn(t[tx][r]);
    }
}

// ---------------------------------------------------------------------------
// fp16 tensor-core GEMM mainloop body
// CTA tile TM x 128, BK=32, 8 warps (warp tile (TM/2) x 32), 3-stage cp.async,
// single __syncthreads per k-iteration, 3 CTAs/SM at TM=64.
// ---------------------------------------------------------------------------
template<int HALF_OUT, int TM>
__device__ __forceinline__
void gemm_body(int tid, uint32_t sb, uint64_t gA, uint64_t gB,
               int m0, int n0, bool act, const float* bias, void* Cg)
{
    constexpr int SROWB  = 80;
    constexpr int ATILEB = TM * SROWB;
    constexpr int BTILEB = 128 * SROWB;
    constexpr int STAGEB = ATILEB + BTILEB;
    constexpr int NIT    = DD / 32;
    constexpr int MF     = TM / 32;          // m16-fragments per warp

    const int lane = tid & 31;
    const int wid = tid >> 5;
    const int wm = wid & 1;                  // M half
    const int wn = wid >> 1;                 // 32-col slab
    const uint32_t aOff = (uint32_t)(wm * (TM / 2) + (lane & 15)) * SROWB
                        + (uint32_t)(lane >> 4) * 16;
    const uint32_t bOff = (uint32_t)(wn * 32 + (lane & 7) + ((lane >> 4) << 3)) * SROWB
                        + (uint32_t)((lane >> 3) & 1) * 16;

    float acc[MF][4][4];
    #pragma unroll
    for (int i = 0; i < MF; i++)
        #pragma unroll
        for (int j = 0; j < 4; j++)
            #pragma unroll
            for (int q = 0; q < 4; q++) acc[i][j][q] = 0.f;

    auto load_stage = [&](int slot, int kc) {
        const uint32_t sbase = sb + slot * STAGEB;
        #pragma unroll
        for (int j = 0; j < TM * 4 / 256; j++) {     // A: TM rows x 4 chunks
            const int idx = tid + 256 * j;
            const int row = idx >> 2, k = idx & 3;
            CP_ASYNC16(sbase + row * SROWB + k * 16,
                       gA + ((size_t)(m0 + row) * DD + kc + k * 8) * 2);
        }
        #pragma unroll
        for (int j = 0; j < 2; j++) {                // B: 128 rows x 4 chunks
            const int idx = tid + 256 * j;
            const int row = idx >> 2, k = idx & 3;
            CP_ASYNC16(sbase + ATILEB + row * SROWB + k * 16,
                       gB + ((size_t)(n0 + row) * DD + kc + k * 8) * 2);
        }
    };

    load_stage(0, 0);  CP_COMMIT();
    load_stage(1, 32); CP_COMMIT();

    for (int it = 0; it < NIT; it++) {
        if (it + 1 < NIT) { CP_WAIT(1); } else { CP_WAIT(0); }
        __syncthreads();
        if (it + 2 < NIT) { load_stage((it + 2) % 3, (it + 2) * 32); CP_COMMIT(); }

        const int slot = it % 3;
        const uint32_t sA = sb + slot * STAGEB;
        const uint32_t sB = sA + ATILEB;

        #pragma unroll
        for (int k16 = 0; k16 < 2; k16++) {
            const uint32_t kb = k16 * 32;
            uint32_t ah[MF][4];
            #pragma unroll
            for (int mf = 0; mf < MF; mf++) {
                const uint32_t ao = aOff + mf * 16 * SROWB + kb;
                LDSM_X4(ah[mf][0], ah[mf][1], ah[mf][2], ah[mf][3], sA + ao);
            }
            uint32_t bb[2][4];
            #pragma unroll
            for (int gg = 0; gg < 2; gg++) {
                const uint32_t bo = bOff + gg * 16 * SROWB + kb;
                LDSM_X4(bb[gg][0], bb[gg][1], bb[gg][2], bb[gg][3], sB + bo);
            }
            #pragma unroll
            for (int mf = 0; mf < MF; mf++) {
                #pragma unroll
                for (int nf = 0; nf < 4; nf++) {
                    const int gg = nf >> 1, p = (nf & 1) * 2;
                    MMA16816F16(acc[mf][nf], ah[mf], bb[gg][p], bb[gg][p + 1]);
                }
            }
        }
    }

    #pragma unroll
    for (int nf = 0; nf < 4; nf++) {
        const int cg = n0 + wn * 32 + nf * 8 + (lane & 3) * 2;
        const float b0 = __ldg(&bias[cg]);
        const float b1 = __ldg(&bias[cg + 1]);
        #pragma unroll
        for (int mf = 0; mf < MF; mf++) {
            const int rg = m0 + wm * (TM / 2) + mf * 16 + (lane >> 2);
            float v0 = acc[mf][nf][0] + b0;
            float v1 = acc[mf][nf][1] + b1;
            float v2 = acc[mf][nf][2] + b0;
            float v3 = acc[mf][nf][3] + b1;
            if (act) {
                v0 = (v0 > 0.f) ? (v0 + 1.f) : __expf(v0);
                v1 = (v1 > 0.f) ? (v1 + 1.f) : __expf(v1);
                v2 = (v2 > 0.f) ? (v2 + 1.f) : __expf(v2);
                v3 = (v3 > 0.f) ? (v3 + 1.f) : __expf(v3);
            }
            if (HALF_OUT) {
                __half* Ch = (__half*)Cg;
                *(__half2*)(Ch + (size_t)rg * DD + cg)       = __floats2half2_rn(v0, v1);
                *(__half2*)(Ch + (size_t)(rg + 8) * DD + cg) = __floats2half2_rn(v2, v3);
            } else {
                float* Cf = (float*)Cg;
                *(float2*)(Cf + (size_t)rg * DD + cg)       = make_float2(v0, v1);
                *(float2*)(Cf + (size_t)(rg + 8) * DD + cg) = make_float2(v2, v3);
            }
        }
    }
}

#define GTM 64   // GEMM M-tile

// Fused Q/K/V projections: grid.x = 3*8 (which*8 + nblk), grid.y = MTOT/GTM
__global__ __launch_bounds__(256, 3)
void qkv_gemm_k(const __half* __restrict__ A, const __half* __restrict__ wT,
                const float* __restrict__ bq, const float* __restrict__ bk,
                const float* __restrict__ bv)
{
    extern __shared__ char smem[];
    const int which = blockIdx.x >> 3;
    const int n0 = (blockIdx.x & 7) * 128;
    const int m0 = blockIdx.y * GTM;
    const __half* BT = wT + (size_t)which * DD * DD;
    const float* bias = (which == 0) ? bq : (which == 1) ? bk : bv;
    __half* out = (which == 0) ? g_qh : (which == 1) ? g_kh : g_vh;
    gemm_body<1, GTM>(threadIdx.x, smem_u32(smem), __cvta_generic_to_global(A),
                      __cvta_generic_to_global(BT), m0, n0, which < 2, bias, out);
}

// Output projection: fp16 A, fp32 C
__global__ __launch_bounds__(256, 3)
void out_gemm_k(const __half* __restrict__ A, const __half* __restrict__ BT,
                const float* __restrict__ bias, float* __restrict__ Cg)
{
    extern __shared__ char smem[];
    gemm_body<0, GTM>(threadIdx.x, smem_u32(smem), __cvta_generic_to_global(A),
                      __cvta_generic_to_global(BT), blockIdx.y * GTM,
                      blockIdx.x * 128, false, bias, Cg);
}

// ---------------------------------------------------------------------------
// Async tile loaders: 64x64 fp16 -> smem [64][LDT] via cp.async (no register
// round-trip, full-tile MLP). Row strides DD (qkvh) and HD (prefix state).
// ---------------------------------------------------------------------------
__device__ __forceinline__
void load_tile_cp(uint32_t dst_s, const __half* src, size_t rowbase, int tid)
{
    #pragma unroll
    for (int j = 0; j < 4; j++) {
        const int idx = tid + 128 * j;
        const int row = idx >> 3;
        const int c = (idx & 7) * 8;
        CP_ASYNC16(dst_s + (uint32_t)(row * LDT + c) * 2,
                   (const void*)(src + rowbase + (size_t)row * DD + c));
    }
}
__device__ __forceinline__
void load_tile_cp_s(uint32_t dst_s, const __half* src, int tid)
{
    #pragma unroll
    for (int j = 0; j < 4; j++) {
        const int idx = tid + 128 * j;
        const int row = idx >> 3;
        const int c = (idx & 7) * 8;
        CP_ASYNC16(dst_s + (uint32_t)(row * LDT + c) * 2,
                   (const void*)(src + (size_t)row * HD + c));
    }
}

// ---------------------------------------------------------------------------
// Pass A (tensor core): KV_c[d][m] = sum_t K[t][d] V[t][m] (fp16 out);
// ks_c[d] = sum_t K[t][d] (fp32)
// ---------------------------------------------------------------------------
__global__ __launch_bounds__(128)
void kv_chunk_tc()
{
    __shared__ __half Ks[CHUNK][LDT];
    __shared__ __half Vs[CHUNK][LDT];

    const int c = blockIdx.x, bh = blockIdx.y;
    const int b = bh >> 4, h = bh & 15;
    const int tid = threadIdx.x;
    const int w = tid >> 5, l = tid & 31;
    const size_t rowbase = (size_t)(b * SEQ + c * CHUNK) * DD + h * HD;

    load_tile_cp(smem_u32(Ks), g_kh, rowbase, tid);
    load_tile_cp(smem_u32(Vs), g_vh, rowbase, tid);
    CP_COMMIT();
    CP_WAIT(0);
    __syncthreads();

    const int tRow = ((l >> 4) << 3) + (l & 7);
    const int tColA = ((l >> 3) & 1) * 8;
    const int tRowB = ((l >> 3) & 1) * 8 + (l & 7);
    const int tColB = (l >> 4) * 8;

    float acc[8][4];
    #pragma unroll
    for (int i = 0; i < 8; i++)
        #pragma unroll
        for (int q = 0; q < 4; q++) acc[i][q] = 0.f;

    #pragma unroll
    for (int kk = 0; kk < 4; kk++) {
        uint32_t a[4];
        LDSM_X4_T(a[0], a[1], a[2], a[3],
                  smem_u32(&Ks[kk * 16 + tRow][w * 16 + tColA]));
        #pragma unroll
        for (int gN = 0; gN < 4; gN++) {
            uint32_t r0, r1, r2, r3;
            LDSM_X4_T(r0, r1, r2, r3,
                      smem_u32(&Vs[kk * 16 + tRowB][gN * 16 + tColB]));
            MMA16816F16(acc[2 * gN],     a, r0, r1);
            MMA16816F16(acc[2 * gN + 1], a, r2, r3);
        }
    }

    __half* outp = g_KVh + (size_t)(bh * NCHUNK + c) * HD * HD;
    const int r0 = w * 16 + (l >> 2);
    #pragma unroll
    for (int nf = 0; nf < 8; nf++) {
        const int col = nf * 8 + 2 * (l & 3);
        *(uint32_t*)(outp + (size_t)r0 * HD + col)       = packh2(acc[nf][0], acc[nf][1]);
        *(uint32_t*)(outp + (size_t)(r0 + 8) * HD + col) = packh2(acc[nf][2], acc[nf][3]);
    }

    if (tid < HD) {
        float s = 0.f;
        #pragma unroll 8
        for (int t = 0; t < CHUNK; t++) s += __half2float(Ks[t][tid]);
        g_KS[(bh * NCHUNK + c) * HD + tid] = s;
    }
}

// ---------------------------------------------------------------------------
// Pass B: in-place EXCLUSIVE prefix over chunks. 8 CTAs per bh; each thread
// owns one half2 lane. All 32 chunk values preloaded into registers (MLP=32),
// scan in registers, then store.
// ---------------------------------------------------------------------------
__global__ __launch_bounds__(256)
void prefix_k()
{
    const int bh = blockIdx.x >> 3;
    const int pos = (blockIdx.x & 7) * 256 + threadIdx.x;   // 0..2047 half2 lanes
    __half* base = g_KVh + (size_t)bh * NCHUNK * HD * HD + pos * 2;

    uint32_t v[NCHUNK];
    #pragma unroll
    for (int c = 0; c < NCHUNK; c++)
        v[c] = *(const uint32_t*)(base + (size_t)c * HD * HD);

    float rx = 0.f, ry = 0.f;
    #pragma unroll
    for (int c = 0; c < NCHUNK; c++) {
        float2 f = __half22float2(*(__half2*)&v[c]);
        *(uint32_t*)(base + (size_t)c * HD * HD) = packh2(rx, ry);
        rx += f.x; ry += f.y;
    }

    if ((blockIdx.x & 7) == 0 && threadIdx.x < HD) {
        float* zb = g_KS + (size_t)bh * NCHUNK * HD + threadIdx.x;
        float zv[NCHUNK];
        #pragma unroll
        for (int c = 0; c < NCHUNK; c++) zv[c] = zb[(size_t)c * HD];
        float r = 0.f;
        #pragma unroll
        for (int c = 0; c < NCHUNK; c++) {
            zb[(size_t)c * HD] = r;
            r += zv[c];
        }
    }
}

// ---------------------------------------------------------------------------
// Pass C (tensor core): out = (tril(QK^T) V + Q S_prev) / (rowsum + Q.z + eps)
// ---------------------------------------------------------------------------
__global__ __launch_bounds__(128)
void attn_out_tc()
{
    __shared__ __half Qs [CHUNK][LDT];
    __shared__ __half Ks [CHUNK][LDT];
    __shared__ __half Vs [CHUNK][LDT];
    __shared__ __half Sph[HD][LDT];
    __shared__ float rs[CHUNK], den[CHUNK], zp[HD];

    const int c = blockIdx.x, bh = blockIdx.y;
    const int b = bh >> 4, h = bh & 15;
    const int tid = threadIdx.x;
    const int w = tid >> 5, l = tid & 31;
    const size_t rowbase = (size_t)(b * SEQ + c * CHUNK) * DD + h * HD;
    const __half* Sp = g_KVh + (size_t)(bh * NCHUNK + c) * HD * HD;

    load_tile_cp(smem_u32(Qs), g_qh, rowbase, tid);
    load_tile_cp(smem_u32(Ks), g_kh, rowbase, tid);
    load_tile_cp(smem_u32(Vs), g_vh, rowbase, tid);
    load_tile_cp_s(smem_u32(Sph), Sp, tid);
    CP_COMMIT();
    if (tid < HD) zp[tid] = g_KS[(bh * NCHUNK + c) * HD + tid];
    CP_WAIT(0);
    __syncthreads();

    const uint32_t aRow = w * 16 + (l & 15);
    const uint32_t aK = (l >> 4) * 8;
    const uint32_t bRow = (l & 7) + ((l >> 4) << 3);
    const uint32_t bK = ((l >> 3) & 1) * 8;
    const int tRowB = ((l >> 3) & 1) * 8 + (l & 7);
    const int tColB = (l >> 4) * 8;

    // Phase 1: S = Q K^T
    float accS[8][4];
    #pragma unroll
    for (int i = 0; i < 8; i++)
        #pragma unroll
        for (int q = 0; q < 4; q++) accS[i][q] = 0.f;

    #pragma unroll
    for (int kk = 0; kk < 4; kk++) {
        uint32_t a[4];
        LDSM_X4(a[0], a[1], a[2], a[3], smem_u32(&Qs[aRow][kk * 16 + aK]));
        #pragma unroll
        for (int gN = 0; gN < 4; gN++) {
            uint32_t r0, r1, r2, r3;
            LDSM_X4(r0, r1, r2, r3, smem_u32(&Ks[gN * 16 + bRow][kk * 16 + bK]));
            MMA16816F16(accS[2 * gN],     a, r0, r1);
            MMA16816F16(accS[2 * gN + 1], a, r2, r3);
        }
    }

    const int row0 = w * 16 + (l >> 2);
    const int row1 = row0 + 8;
    float sum0 = 0.f, sum1 = 0.f;
    #pragma unroll
    for (int nf = 0; nf < 8; nf++) {
        #pragma unroll
        for (int jj = 0; jj < 2; jj++) {
            const int col = nf * 8 + 2 * (l & 3) + jj;
            accS[nf][jj]     = (col <= row0) ? accS[nf][jj]     : 0.f;
            accS[nf][2 + jj] = (col <= row1) ? accS[nf][2 + jj] : 0.f;
            sum0 += accS[nf][jj];
            sum1 += accS[nf][2 + jj];
        }
    }
    sum0 += __shfl_xor_sync(0xFFFFFFFF, sum0, 1);
    sum0 += __shfl_xor_sync(0xFFFFFFFF, sum0, 2);
    sum1 += __shfl_xor_sync(0xFFFFFFFF, sum1, 1);
    sum1 += __shfl_xor_sync(0xFFFFFFFF, sum1, 2);
    if ((l & 3) == 0) { rs[row0] = sum0; rs[row1] = sum1; }
    __syncthreads();
    if (tid < CHUNK) {
        float qz = 0.f;
        #pragma unroll 8
        for (int d = 0; d < HD; d++) qz = fmaf(__half2float(Qs[tid][d]), zp[d], qz);
        den[tid] = rs[tid] + qz + 1e-6f;
    }
    __syncthreads();

    // Phase 2: O = S V + Q S_prev
    float accO[8][4];
    #pragma unroll
    for (int i = 0; i < 8; i++)
        #pragma unroll
        for (int q = 0; q < 4; q++) accO[i][q] = 0.f;

    #pragma unroll
    for (int kk = 0; kk < 4; kk++) {
        uint32_t a[4];
        a[0] = packh2(accS[2 * kk][0],     accS[2 * kk][1]);
        a[1] = packh2(accS[2 * kk][2],     accS[2 * kk][3]);
        a[2] = packh2(accS[2 * kk + 1][0], accS[2 * kk + 1][1]);
        a[3] = packh2(accS[2 * kk + 1][2], accS[2 * kk + 1][3]);
        #pragma unroll
        for (int gN = 0; gN < 4; gN++) {
            uint32_t r0, r1, r2, r3;
            LDSM_X4_T(r0, r1, r2, r3,
                      smem_u32(&Vs[kk * 16 + tRowB][gN * 16 + tColB]));
            MMA16816F16(accO[2 * gN],     a, r0, r1);
            MMA16816F16(accO[2 * gN + 1], a, r2, r3);
        }
    }
    #pragma unroll
    for (int kk = 0; kk < 4; kk++) {
        uint32_t a[4];
        LDSM_X4(a[0], a[1], a[2], a[3], smem_u32(&Qs[aRow][kk * 16 + aK]));
        #pragma unroll
        for (int gN = 0; gN < 4; gN++) {
            uint32_t r0, r1, r2, r3;
            LDSM_X4_T(r0, r1, r2, r3,
                      smem_u32(&Sph[kk * 16 + tRowB][gN * 16 + tColB]));
            MMA16816F16(accO[2 * gN],     a, r0, r1);
            MMA16816F16(accO[2 * gN + 1], a, r2, r3);
        }
    }

    const float inv0 = 1.0f / den[row0];
    const float inv1 = 1.0f / den[row1];
    #pragma unroll
    for (int nf = 0; nf < 8; nf++) {
        const int col = nf * 8 + 2 * (l & 3);
        *(uint32_t*)(g_valh + rowbase + (size_t)row0 * DD + col) =
            packh2(accO[nf][0] * inv0, accO[nf][1] * inv0);
        *(uint32_t*)(g_valh + rowbase + (size_t)row1 * DD + col) =
            packh2(accO[nf][2] * inv1, accO[nf][3] * inv1);
    }
}

// ---------------------------------------------------------------------------
extern "C" void kernel_launch(void* const* d_in, const int* in_sizes, int n_in,
                              void* d_out, int out_size)
{
    (void)in_sizes; (void)n_in; (void)out_size;
    const float* x  = (const float*)d_in[0];
    const float* Wq = (const float*)d_in[2];
    const float* bq = (const float*)d_in[3];
    const float* Wk = (const float*)d_in[4];
    const float* bk = (const float*)d_in[5];
    const float* Wv = (const float*)d_in[6];
    const float* bv = (const float*)d_in[7];
    const float* Wo = (const float*)d_in[8];
    const float* bo = (const float*)d_in[9];
    float* out = (float*)d_out;

    __half *pxh, *pvalh, *pwT;
    cudaGetSymbolAddress((void**)&pxh,   g_xh);
    cudaGetSymbolAddress((void**)&pvalh, g_valh);
    cudaGetSymbolAddress((void**)&pwT,   g_wT);

    const int smbytes_g = 3 * (GTM + 128) * 80;   // 46080 (3 stages x (A+B))
    cudaFuncSetAttribute(qkv_gemm_k, cudaFuncAttributeMaxDynamicSharedMemorySize, smbytes_g);
    cudaFuncSetAttribute(out_gemm_k, cudaFuncAttributeMaxDynamicSharedMemorySize, smbytes_g);

    // fp32->fp16 conversions (x + all 4 weight transposes, one launch)
    const int n8 = MTOT * DD / 8;
    conv_all_k<<<NCVH + 4096, 256>>>((const float4*)x, (uint4*)pxh, n8,
                                     Wq, Wk, Wv, Wo, pwT);

    // fused Q/K/V projections (TM=64 tiles -> 3072 CTAs)
    qkv_gemm_k<<<dim3(3 * DD / 128, MTOT / GTM), 256, smbytes_g>>>(pxh, pwT, bq, bk, bv);

    // linear attention (tensor-core passes, fp16 state)
    dim3 agrid(NCHUNK, NBH);
    kv_chunk_tc<<<agrid, 128>>>();
    prefix_k<<<NBH * 8, 256>>>();
    attn_out_tc<<<agrid, 128>>>();

    // output projection -> fp32 out (1024 CTAs)
    out_gemm_k<<<dim3(DD / 128, MTOT / GTM), 256, smbytes_g>>>(
        pvalh, pwT + 3 * (size_t)DD * DD, bo, out);
}